// round 1
// baseline (speedup 1.0000x reference)
#include <cuda_runtime.h>

#define B_ 256
#define N_ 5
#define D_ 2048
#define C_ 1000
#define H_ 1024
#define PROTO_M 0.999f
#define EPS_ 1e-12f

// ---------------- scratch (static device globals; no allocation) ----------------
__device__ float g_ax[B_ * N_ * D_];     // adj @ x            [256,5,2048]
__device__ float g_h[B_ * N_ * H_];      // relu(ax @ W1)      [256,5,1024]
__device__ float g_ah[B_ * N_ * H_];     // adj @ h            [256,5,1024]
__device__ float g_nodes[B_ * N_ * D_];  // ah @ W2            [256,5,2048]
__device__ float g_g[B_ * D_];           // fc_g output        [256,2048]

__device__ float g_scale[C_];            // m^{k_c}
__device__ int   g_off[C_ + 1];          // CSR offsets
__device__ int   g_idx[B_];              // sample index sorted by class (stable)
__device__ float g_w[B_];                // per-sample EMA weight

// ---------------- adj mix: out[b,n,f] = sum_m adj[n,m] * in[b,m,f] ----------------
__global__ void adj_mix_kernel(const float* __restrict__ in,
                               const float* __restrict__ adj,
                               float* __restrict__ out, int F) {
    int t = blockIdx.x * blockDim.x + threadIdx.x;
    if (t >= B_ * F) return;
    int b = t / F, f = t % F;
    float xv[N_];
#pragma unroll
    for (int m = 0; m < N_; m++) xv[m] = in[(b * N_ + m) * F + f];
#pragma unroll
    for (int n = 0; n < N_; n++) {
        float s = 0.f;
#pragma unroll
        for (int m = 0; m < N_; m++) s += adj[n * N_ + m] * xv[m];
        out[(b * N_ + n) * F + f] = s;
    }
}

// ---------------- tiled fp32 SGEMM: C = A[M,K] @ B[K,N] (+bias, +relu) ----------------
#define BM 64
#define BN 64
#define BK 16

template <bool RELU, bool BIAS>
__global__ void sgemm_kernel(const float* __restrict__ A,
                             const float* __restrict__ Bm,
                             const float* __restrict__ bias,
                             float* __restrict__ Cm,
                             int M, int N, int K) {
    __shared__ float As[BK][BM];
    __shared__ float Bs[BK][BN];

    int tid = threadIdx.x;            // 256 threads
    int tx = tid & 15, ty = tid >> 4; // 16x16
    int row0 = blockIdx.y * BM;
    int col0 = blockIdx.x * BN;

    float acc[4][4] = {};

    for (int k0 = 0; k0 < K; k0 += BK) {
        // A tile: BM x BK -> As[k][m]
#pragma unroll
        for (int l = 0; l < 4; l++) {
            int idx = tid + l * 256;
            int r = idx >> 4, c = idx & 15;
            int gr = row0 + r, gc = k0 + c;
            As[c][r] = (gr < M && gc < K) ? A[(size_t)gr * K + gc] : 0.f;
        }
        // B tile: BK x BN -> Bs[k][n]
#pragma unroll
        for (int l = 0; l < 4; l++) {
            int idx = tid + l * 256;
            int r = idx >> 6, c = idx & 63;
            int gr = k0 + r, gc = col0 + c;
            Bs[r][c] = (gr < K && gc < N) ? Bm[(size_t)gr * N + gc] : 0.f;
        }
        __syncthreads();

#pragma unroll
        for (int k = 0; k < BK; k++) {
            float4 a4 = *reinterpret_cast<const float4*>(&As[k][ty * 4]);
            float4 b4 = *reinterpret_cast<const float4*>(&Bs[k][tx * 4]);
            float av[4] = {a4.x, a4.y, a4.z, a4.w};
            float bv[4] = {b4.x, b4.y, b4.z, b4.w};
#pragma unroll
            for (int i = 0; i < 4; i++)
#pragma unroll
                for (int j = 0; j < 4; j++) acc[i][j] += av[i] * bv[j];
        }
        __syncthreads();
    }

#pragma unroll
    for (int i = 0; i < 4; i++) {
        int gr = row0 + ty * 4 + i;
        if (gr >= M) continue;
#pragma unroll
        for (int j = 0; j < 4; j++) {
            int gc = col0 + tx * 4 + j;
            if (gc >= N) continue;
            float v = acc[i][j];
            if (BIAS) v += bias[gc];
            if (RELU) v = fmaxf(v, 0.f);
            Cm[(size_t)gr * N + gc] = v;
        }
    }
}

// ---------------- class metadata: closed-form of the sequential EMA scan ----------------
// final[c] = proto[c]*m^{k_c} + (1-m) * sum_{r=0..k_c-1} m^{k_c-1-r} * x[i_r]
__global__ void class_meta_kernel(const int* __restrict__ target) {
    __shared__ int cnt[C_];
    for (int c = threadIdx.x; c < C_; c += blockDim.x) cnt[c] = 0;
    __syncthreads();
    if (threadIdx.x == 0) {
        int rank[B_];
        for (int i = 0; i < B_; i++) {
            int c = target[i];
            rank[i] = cnt[c]++;
        }
        int off = 0;
        for (int c = 0; c < C_; c++) {
            g_off[c] = off;
            off += cnt[c];
            g_scale[c] = powf(PROTO_M, (float)cnt[c]);
        }
        g_off[C_] = off;
        for (int i = 0; i < B_; i++) {
            int c = target[i];
            int p = g_off[c] + rank[i];
            g_idx[p] = i;
            g_w[p] = (1.0f - PROTO_M) * powf(PROTO_M, (float)(cnt[c] - 1 - rank[i]));
        }
    }
}

// ---------------- fused EMA update + L2 normalize over node axis ----------------
__global__ void proto_update_kernel(const float* __restrict__ x,
                                    const float* __restrict__ protos,
                                    float* __restrict__ out) {
    int t = blockIdx.x * blockDim.x + threadIdx.x;
    if (t >= C_ * D_) return;
    int c = t / D_, d = t % D_;

    float s = g_scale[c];
    float v[N_];
#pragma unroll
    for (int n = 0; n < N_; n++) v[n] = protos[((size_t)c * N_ + n) * D_ + d] * s;

    int e = g_off[c + 1];
    for (int j = g_off[c]; j < e; j++) {
        int i = g_idx[j];
        float w = g_w[j];
#pragma unroll
        for (int n = 0; n < N_; n++) v[n] += w * x[((size_t)i * N_ + n) * D_ + d];
    }

    float nrm = 0.f;
#pragma unroll
    for (int n = 0; n < N_; n++) nrm += v[n] * v[n];
    nrm = sqrtf(nrm);
    float inv = 1.0f / fmaxf(nrm, EPS_);
#pragma unroll
    for (int n = 0; n < N_; n++) out[((size_t)c * N_ + n) * D_ + d] = v[n] * inv;
}

// ---------------- launch ----------------
extern "C" void kernel_launch(void* const* d_in, const int* in_sizes, int n_in,
                              void* d_out, int out_size) {
    const float* x    = (const float*)d_in[0];  // [256,5,2048]
    const int*   tgt  = (const int*)d_in[1];    // [256]
    const float* prot = (const float*)d_in[2];  // [1000,5,2048]
    const float* adj  = (const float*)d_in[3];  // [5,5]
    const float* W1   = (const float*)d_in[4];  // [2048,1024]
    const float* W2   = (const float*)d_in[5];  // [1024,2048]
    const float* Wg   = (const float*)d_in[6];  // [10240,2048]
    const float* bg   = (const float*)d_in[7];  // [2048]
    const float* Wc   = (const float*)d_in[8];  // [2048,1000]
    const float* bc   = (const float*)d_in[9];  // [1000]

    float* pred_out  = (float*)d_out;                 // [256,1000]
    float* proto_out = (float*)d_out + (size_t)B_ * C_;  // [1000,5,2048]

    float *ax, *h, *ah, *nodes, *g;
    cudaGetSymbolAddress((void**)&ax, g_ax);
    cudaGetSymbolAddress((void**)&h, g_h);
    cudaGetSymbolAddress((void**)&ah, g_ah);
    cudaGetSymbolAddress((void**)&nodes, g_nodes);
    cudaGetSymbolAddress((void**)&g, g_g);

    // 1) ax = adj @ x
    {
        int n = B_ * D_;
        adj_mix_kernel<<<(n + 255) / 256, 256>>>(x, adj, ax, D_);
    }
    // 2) h = relu(ax @ W1)   [1280,2048]@[2048,1024]
    {
        dim3 grid(H_ / BN, (B_ * N_) / BM);
        sgemm_kernel<true, false><<<grid, 256>>>(ax, W1, nullptr, h, B_ * N_, H_, D_);
    }
    // 3) ah = adj @ h
    {
        int n = B_ * H_;
        adj_mix_kernel<<<(n + 255) / 256, 256>>>(h, adj, ah, H_);
    }
    // 4) nodes = ah @ W2     [1280,1024]@[1024,2048]
    {
        dim3 grid(D_ / BN, (B_ * N_) / BM);
        sgemm_kernel<false, false><<<grid, 256>>>(ah, W2, nullptr, nodes, B_ * N_, D_, H_);
    }
    // 5) g = nodes.reshape(256,10240) @ Wg + bg
    {
        dim3 grid(D_ / BN, B_ / BM);
        sgemm_kernel<false, true><<<grid, 256>>>(nodes, Wg, bg, g, B_, D_, N_ * D_);
    }
    // 6) pred = g @ Wc + bc  -> d_out[0 : 256*1000]
    {
        dim3 grid((C_ + BN - 1) / BN, B_ / BM);
        sgemm_kernel<false, true><<<grid, 256>>>(g, Wc, bc, pred_out, B_, C_, D_);
    }
    // 7) class metadata (closed form of sequential EMA)
    class_meta_kernel<<<1, 256>>>(tgt);
    // 8) fused EMA update + normalize -> d_out[256*1000 : ]
    {
        int n = C_ * D_;
        proto_update_kernel<<<(n + 255) / 256, 256>>>(x, prot, proto_out);
    }
}

// round 3
// speedup vs baseline: 2.6506x; 2.6506x over previous
#include <cuda_runtime.h>
#include <cuda_bf16.h>
#include <cstdint>

#define B_ 256
#define N_ 5
#define D_ 2048
#define C_ 1000
#define H_ 1024
#define NPAD_C 1024
#define PROTO_M 0.999f
#define EPS_ 1e-12f

#define KB 32        // k-chunk per pipeline stage
#define ASTRIDE 40   // smem row stride in bf16 elems (80B) -> conflict-free

// ==================== scratch (static device globals) ====================
__device__ __nv_bfloat16 g_ax_hi[B_ * N_ * D_], g_ax_lo[B_ * N_ * D_];
__device__ __nv_bfloat16 g_ah_hi[B_ * N_ * H_], g_ah_lo[B_ * N_ * H_];
__device__ __nv_bfloat16 g_nd_hi[B_ * N_ * D_], g_nd_lo[B_ * N_ * D_];
__device__ __nv_bfloat16 g_g_hi[B_ * D_], g_g_lo[B_ * D_];
__device__ __nv_bfloat16 g_W1t_hi[H_ * D_], g_W1t_lo[H_ * D_];
__device__ __nv_bfloat16 g_W2t_hi[D_ * H_], g_W2t_lo[D_ * H_];
__device__ __nv_bfloat16 g_Wgt_hi[D_ * N_ * D_], g_Wgt_lo[D_ * N_ * D_];
__device__ __nv_bfloat16 g_Wct_hi[NPAD_C * D_], g_Wct_lo[NPAD_C * D_];
__device__ float g_part[16 * B_ * D_];   // split-K partials (max 16x256x2048 = 33MB)

__device__ float g_scale[C_];
__device__ int   g_off[C_ + 1];
__device__ int   g_idx[B_];
__device__ float g_w[B_];

// ==================== helpers ====================
__device__ __forceinline__ void split_bf16(float v, __nv_bfloat16& hi, __nv_bfloat16& lo) {
    hi = __float2bfloat16_rn(v);
    lo = __float2bfloat16_rn(v - __bfloat162float(hi));
}
__device__ __forceinline__ uint32_t smem_u32(const void* p) {
    uint32_t a;
    asm("{ .reg .u64 t; cvta.to.shared.u64 t, %1; cvt.u32.u64 %0, t; }" : "=r"(a) : "l"(p));
    return a;
}
__device__ __forceinline__ void cp_async16(uint32_t dst, const void* src) {
    asm volatile("cp.async.cg.shared.global [%0], [%1], 16;" :: "r"(dst), "l"(src));
}
__device__ __forceinline__ void cp_commit() { asm volatile("cp.async.commit_group;" ::: "memory"); }
__device__ __forceinline__ void cp_wait1() { asm volatile("cp.async.wait_group 1;" ::: "memory"); }
__device__ __forceinline__ void cp_wait0() { asm volatile("cp.async.wait_group 0;" ::: "memory"); }

__device__ __forceinline__ void mma16816(float* c, uint32_t a0, uint32_t a1, uint32_t a2,
                                         uint32_t a3, uint32_t b0, uint32_t b1) {
    asm volatile(
        "mma.sync.aligned.m16n8k16.row.col.f32.bf16.bf16.f32 "
        "{%0,%1,%2,%3}, {%4,%5,%6,%7}, {%8,%9}, {%0,%1,%2,%3};"
        : "+f"(c[0]), "+f"(c[1]), "+f"(c[2]), "+f"(c[3])
        : "r"(a0), "r"(a1), "r"(a2), "r"(a3), "r"(b0), "r"(b1));
}

// ==================== weight transpose + hi/lo convert ====================
// W [K,N] f32 -> Wt [Npad,K] bf16 (hi,lo); rows n>=N zero-padded.
__global__ void transpose_convert_kernel(const float* __restrict__ W,
                                         __nv_bfloat16* __restrict__ hi,
                                         __nv_bfloat16* __restrict__ lo,
                                         int K, int N) {
    __shared__ float t[32][33];
    int kb = blockIdx.x * 32, nb = blockIdx.y * 32;
    int tx = threadIdx.x, ty = threadIdx.y;  // 32 x 8
#pragma unroll
    for (int j = 0; j < 4; j++) {
        int k = kb + ty + 8 * j, n = nb + tx;
        t[ty + 8 * j][tx] = (n < N) ? W[(size_t)k * N + n] : 0.f;
    }
    __syncthreads();
#pragma unroll
    for (int j = 0; j < 4; j++) {
        int n = nb + ty + 8 * j, k = kb + tx;
        float v = t[tx][ty + 8 * j];
        __nv_bfloat16 h, l;
        split_bf16(v, h, l);
        hi[(size_t)n * K + k] = h;
        lo[(size_t)n * K + k] = l;
    }
}

// ==================== adj-mix + hi/lo convert ====================
__global__ void adjmix_convert_kernel(const float* __restrict__ in,
                                      const float* __restrict__ adj,
                                      __nv_bfloat16* __restrict__ hi,
                                      __nv_bfloat16* __restrict__ lo, int F) {
    int t = blockIdx.x * blockDim.x + threadIdx.x;
    if (t >= B_ * F) return;
    int b = t / F, f = t % F;
    float xv[N_];
#pragma unroll
    for (int m = 0; m < N_; m++) xv[m] = in[((size_t)b * N_ + m) * F + f];
#pragma unroll
    for (int n = 0; n < N_; n++) {
        float s = 0.f;
#pragma unroll
        for (int m = 0; m < N_; m++) s += adj[n * N_ + m] * xv[m];
        __nv_bfloat16 h, l;
        split_bf16(s, h, l);
        hi[((size_t)b * N_ + n) * F + f] = h;
        lo[((size_t)b * N_ + n) * F + f] = l;
    }
}

// ==================== HMMA bf16 hi/lo split-K GEMM ====================
// P[s] += A[M,K] @ Bt[N,K]^T over chunk range; virtual K'=3K
// (seg0 hiA*hiB, seg1 hiA*loB, seg2 loA*hiB). Grid (N/128, M/128, S), 256 thr.
__global__ void __launch_bounds__(256, 1)
gemm_hl_mma(const __nv_bfloat16* __restrict__ A_hi, const __nv_bfloat16* __restrict__ A_lo,
            const __nv_bfloat16* __restrict__ B_hi, const __nv_bfloat16* __restrict__ B_lo,
            float* __restrict__ P, int M, int N, int K, int NCper) {
    __shared__ __nv_bfloat16 sA[2][128 * ASTRIDE];
    __shared__ __nv_bfloat16 sB[2][128 * ASTRIDE];

    const int tid = threadIdx.x;
    const int warp = tid >> 5, lane = tid & 31;
    const int wr = warp & 3, wc = warp >> 2;       // 4x2 warp grid
    const int g = lane >> 2, tg = lane & 3;
    const int row0 = blockIdx.y * 128, col0 = blockIdx.x * 128;
    const int KC = K / KB;
    const int c0 = blockIdx.z * NCper;

    const uint32_t sA0 = smem_u32(sA[0]), sA1 = smem_u32(sA[1]);
    const uint32_t sB0 = smem_u32(sB[0]), sB1 = smem_u32(sB[1]);

    float acc[2][8][4];
#pragma unroll
    for (int i = 0; i < 2; i++)
#pragma unroll
        for (int j = 0; j < 8; j++)
#pragma unroll
            for (int k = 0; k < 4; k++) acc[i][j][k] = 0.f;

    // per-thread cp.async assignments: idx = tid + i*256 -> row idx>>2, quad idx&3
    const int r0 = (tid) >> 2, q0 = (tid) & 3;
    const int r1 = (tid + 256) >> 2, q1 = (tid + 256) & 3;

    auto load_chunk = [&](int c, int buf) {
        int seg = c / KC;
        int kk = (c - seg * KC) * KB;
        const __nv_bfloat16* Ap = (seg == 2) ? A_lo : A_hi;
        const __nv_bfloat16* Bp = (seg == 1) ? B_lo : B_hi;
        uint32_t da = buf ? sA1 : sA0;
        uint32_t db = buf ? sB1 : sB0;
        cp_async16(da + (uint32_t)(r0 * ASTRIDE + q0 * 8) * 2,
                   Ap + (size_t)(row0 + r0) * K + kk + q0 * 8);
        cp_async16(da + (uint32_t)(r1 * ASTRIDE + q1 * 8) * 2,
                   Ap + (size_t)(row0 + r1) * K + kk + q1 * 8);
        cp_async16(db + (uint32_t)(r0 * ASTRIDE + q0 * 8) * 2,
                   Bp + (size_t)(col0 + r0) * K + kk + q0 * 8);
        cp_async16(db + (uint32_t)(r1 * ASTRIDE + q1 * 8) * 2,
                   Bp + (size_t)(col0 + r1) * K + kk + q1 * 8);
    };

    load_chunk(c0, 0);
    cp_commit();

    for (int li = 0; li < NCper; li++) {
        if (li + 1 < NCper) {
            load_chunk(c0 + li + 1, (li + 1) & 1);
            cp_commit();
            cp_wait1();
        } else {
            cp_wait0();
        }
        __syncthreads();

        const __nv_bfloat16* Ab = sA[li & 1];
        const __nv_bfloat16* Bb = sB[li & 1];
#pragma unroll
        for (int ks = 0; ks < 2; ks++) {
            const int kb = ks * 16;
            uint32_t bf[8][2];
#pragma unroll
            for (int ni = 0; ni < 8; ni++) {
                int n = wc * 64 + ni * 8 + g;
                const __nv_bfloat16* bp = Bb + n * ASTRIDE + kb + tg * 2;
                bf[ni][0] = *reinterpret_cast<const uint32_t*>(bp);
                bf[ni][1] = *reinterpret_cast<const uint32_t*>(bp + 8);
            }
#pragma unroll
            for (int mi = 0; mi < 2; mi++) {
                int r = wr * 32 + mi * 16 + g;
                const __nv_bfloat16* ap = Ab + r * ASTRIDE + kb + tg * 2;
                uint32_t a0 = *reinterpret_cast<const uint32_t*>(ap);
                uint32_t a1 = *reinterpret_cast<const uint32_t*>(ap + 8 * ASTRIDE);
                uint32_t a2 = *reinterpret_cast<const uint32_t*>(ap + 8);
                uint32_t a3 = *reinterpret_cast<const uint32_t*>(ap + 8 * ASTRIDE + 8);
#pragma unroll
                for (int ni = 0; ni < 8; ni++)
                    mma16816(acc[mi][ni], a0, a1, a2, a3, bf[ni][0], bf[ni][1]);
            }
        }
        __syncthreads();
    }

    // epilogue: write f32 partial
    size_t base = (size_t)blockIdx.z * M * N;
#pragma unroll
    for (int mi = 0; mi < 2; mi++) {
#pragma unroll
        for (int half = 0; half < 2; half++) {
            int r = row0 + wr * 32 + mi * 16 + g + half * 8;
            float* rowp = P + base + (size_t)r * N + col0 + wc * 64;
#pragma unroll
            for (int ni = 0; ni < 8; ni++) {
                float2 v = make_float2(acc[mi][ni][half * 2], acc[mi][ni][half * 2 + 1]);
                *reinterpret_cast<float2*>(rowp + ni * 8 + tg * 2) = v;
            }
        }
    }
}

// ==================== reduce epilogues ====================
__global__ void reduce_relu_adjmix_convert_kernel(const float* __restrict__ P, int S,
                                                  const float* __restrict__ adj,
                                                  __nv_bfloat16* __restrict__ hi,
                                                  __nv_bfloat16* __restrict__ lo, int F) {
    int t = blockIdx.x * blockDim.x + threadIdx.x;
    if (t >= B_ * F) return;
    int b = t / F, f = t % F;
    float hv[N_];
#pragma unroll
    for (int m = 0; m < N_; m++) {
        float s = 0.f;
        for (int j = 0; j < S; j++)
            s += P[(size_t)j * (B_ * N_ * F) + ((size_t)b * N_ + m) * F + f];
        hv[m] = fmaxf(s, 0.f);
    }
#pragma unroll
    for (int n = 0; n < N_; n++) {
        float s = 0.f;
#pragma unroll
        for (int m = 0; m < N_; m++) s += adj[n * N_ + m] * hv[m];
        __nv_bfloat16 h, l;
        split_bf16(s, h, l);
        hi[((size_t)b * N_ + n) * F + f] = h;
        lo[((size_t)b * N_ + n) * F + f] = l;
    }
}

__global__ void reduce_convert_kernel(const float* __restrict__ P, int S, size_t len,
                                      __nv_bfloat16* __restrict__ hi,
                                      __nv_bfloat16* __restrict__ lo) {
    size_t t = (size_t)blockIdx.x * blockDim.x + threadIdx.x;
    if (t >= len) return;
    float s = 0.f;
    for (int j = 0; j < S; j++) s += P[(size_t)j * len + t];
    __nv_bfloat16 h, l;
    split_bf16(s, h, l);
    hi[t] = h;
    lo[t] = l;
}

__global__ void reduce_bias_convert_kernel(const float* __restrict__ P, int S, int M, int N,
                                           const float* __restrict__ bias,
                                           __nv_bfloat16* __restrict__ hi,
                                           __nv_bfloat16* __restrict__ lo) {
    int t = blockIdx.x * blockDim.x + threadIdx.x;
    if (t >= M * N) return;
    float s = bias[t % N];
    for (int j = 0; j < S; j++) s += P[(size_t)j * M * N + t];
    __nv_bfloat16 h, l;
    split_bf16(s, h, l);
    hi[t] = h;
    lo[t] = l;
}

__global__ void reduce_bias_out_kernel(const float* __restrict__ P, int S, int Npad,
                                       const float* __restrict__ bias,
                                       float* __restrict__ out) {
    int t = blockIdx.x * blockDim.x + threadIdx.x;
    if (t >= B_ * C_) return;
    int b = t / C_, n = t % C_;
    float s = bias[n];
    for (int j = 0; j < S; j++) s += P[(size_t)j * B_ * Npad + (size_t)b * Npad + n];
    out[t] = s;
}

// ==================== prototype EMA (closed form), parallel metadata ====================
__global__ void class_meta_kernel(const int* __restrict__ target) {  // 1 block, 1024 thr
    __shared__ int cnt[1024];
    __shared__ int scan[1024];
    __shared__ int t_s[B_];
    __shared__ int rank_s[B_];
    int tid = threadIdx.x;
    cnt[tid] = 0;
    __syncthreads();
    if (tid < B_) t_s[tid] = target[tid];
    __syncthreads();
    if (tid < B_) {
        int c = t_s[tid], r = 0;
        for (int j = 0; j < tid; j++) r += (t_s[j] == c) ? 1 : 0;
        rank_s[tid] = r;
        atomicAdd(&cnt[c], 1);
    }
    __syncthreads();
    if (tid < C_) g_scale[tid] = powf(PROTO_M, (float)cnt[tid]);
    scan[tid] = cnt[tid];
    __syncthreads();
    for (int ofs = 1; ofs < 1024; ofs <<= 1) {
        int v = (tid >= ofs) ? scan[tid - ofs] : 0;
        __syncthreads();
        scan[tid] += v;
        __syncthreads();
    }
    if (tid < C_) g_off[tid] = scan[tid] - cnt[tid];
    if (tid == 0) g_off[C_] = B_;
    __syncthreads();
    if (tid < B_) {
        int c = t_s[tid];
        int p = (scan[c] - cnt[c]) + rank_s[tid];
        g_idx[p] = tid;
        g_w[p] = (1.0f - PROTO_M) * powf(PROTO_M, (float)(cnt[c] - 1 - rank_s[tid]));
    }
}

__global__ void proto_update_kernel(const float* __restrict__ x,
                                    const float* __restrict__ protos,
                                    float* __restrict__ out) {
    int t = blockIdx.x * blockDim.x + threadIdx.x;
    const int D4 = D_ / 4;
    if (t >= C_ * D4) return;
    int c = t / D4, d4 = t % D4;
    float s = g_scale[c];
    float4 v[N_];
#pragma unroll
    for (int n = 0; n < N_; n++) {
        float4 p = *reinterpret_cast<const float4*>(protos + ((size_t)c * N_ + n) * D_ + d4 * 4);
        v[n] = make_float4(p.x * s, p.y * s, p.z * s, p.w * s);
    }
    int e = g_off[c + 1];
    for (int j = g_off[c]; j < e; j++) {
        int i = g_idx[j];
        float w = g_w[j];
#pragma unroll
        for (int n = 0; n < N_; n++) {
            float4 xv = *reinterpret_cast<const float4*>(x + ((size_t)i * N_ + n) * D_ + d4 * 4);
            v[n].x += w * xv.x; v[n].y += w * xv.y;
            v[n].z += w * xv.z; v[n].w += w * xv.w;
        }
    }
    float4 nrm4 = make_float4(0.f, 0.f, 0.f, 0.f);
#pragma unroll
    for (int n = 0; n < N_; n++) {
        nrm4.x += v[n].x * v[n].x; nrm4.y += v[n].y * v[n].y;
        nrm4.z += v[n].z * v[n].z; nrm4.w += v[n].w * v[n].w;
    }
    float4 inv = make_float4(1.f / fmaxf(sqrtf(nrm4.x), EPS_), 1.f / fmaxf(sqrtf(nrm4.y), EPS_),
                             1.f / fmaxf(sqrtf(nrm4.z), EPS_), 1.f / fmaxf(sqrtf(nrm4.w), EPS_));
#pragma unroll
    for (int n = 0; n < N_; n++) {
        float4 o = make_float4(v[n].x * inv.x, v[n].y * inv.y, v[n].z * inv.z, v[n].w * inv.w);
        *reinterpret_cast<float4*>(out + ((size_t)c * N_ + n) * D_ + d4 * 4) = o;
    }
}

// ==================== launch ====================
extern "C" void kernel_launch(void* const* d_in, const int* in_sizes, int n_in,
                              void* d_out, int out_size) {
    const float* x    = (const float*)d_in[0];
    const int*   tgt  = (const int*)d_in[1];
    const float* prot = (const float*)d_in[2];
    const float* adj  = (const float*)d_in[3];
    const float* W1   = (const float*)d_in[4];
    const float* W2   = (const float*)d_in[5];
    const float* Wg   = (const float*)d_in[6];
    const float* bg   = (const float*)d_in[7];
    const float* Wc   = (const float*)d_in[8];
    const float* bc   = (const float*)d_in[9];

    float* pred_out  = (float*)d_out;
    float* proto_out = (float*)d_out + (size_t)B_ * C_;

    __nv_bfloat16 *ax_hi, *ax_lo, *ah_hi, *ah_lo, *nd_hi, *nd_lo, *gg_hi, *gg_lo;
    __nv_bfloat16 *W1t_hi, *W1t_lo, *W2t_hi, *W2t_lo, *Wgt_hi, *Wgt_lo, *Wct_hi, *Wct_lo;
    float* part;
    cudaGetSymbolAddress((void**)&ax_hi, g_ax_hi);   cudaGetSymbolAddress((void**)&ax_lo, g_ax_lo);
    cudaGetSymbolAddress((void**)&ah_hi, g_ah_hi);   cudaGetSymbolAddress((void**)&ah_lo, g_ah_lo);
    cudaGetSymbolAddress((void**)&nd_hi, g_nd_hi);   cudaGetSymbolAddress((void**)&nd_lo, g_nd_lo);
    cudaGetSymbolAddress((void**)&gg_hi, g_g_hi);    cudaGetSymbolAddress((void**)&gg_lo, g_g_lo);
    cudaGetSymbolAddress((void**)&W1t_hi, g_W1t_hi); cudaGetSymbolAddress((void**)&W1t_lo, g_W1t_lo);
    cudaGetSymbolAddress((void**)&W2t_hi, g_W2t_hi); cudaGetSymbolAddress((void**)&W2t_lo, g_W2t_lo);
    cudaGetSymbolAddress((void**)&Wgt_hi, g_Wgt_hi); cudaGetSymbolAddress((void**)&Wgt_lo, g_Wgt_lo);
    cudaGetSymbolAddress((void**)&Wct_hi, g_Wct_hi); cudaGetSymbolAddress((void**)&Wct_lo, g_Wct_lo);
    cudaGetSymbolAddress((void**)&part, g_part);

    dim3 tb(32, 8);
    transpose_convert_kernel<<<dim3(D_ / 32, H_ / 32), tb>>>(W1, W1t_hi, W1t_lo, D_, H_);
    transpose_convert_kernel<<<dim3(H_ / 32, D_ / 32), tb>>>(W2, W2t_hi, W2t_lo, H_, D_);
    transpose_convert_kernel<<<dim3((N_ * D_) / 32, D_ / 32), tb>>>(Wg, Wgt_hi, Wgt_lo, N_ * D_, D_);
    transpose_convert_kernel<<<dim3(D_ / 32, NPAD_C / 32), tb>>>(Wc, Wct_hi, Wct_lo, D_, C_);

    adjmix_convert_kernel<<<(B_ * D_ + 255) / 256, 256>>>(x, adj, ax_hi, ax_lo, D_);

    // GEMM1: [1280,2048]@W1 -> relu -> adjmix; NC=192, S=2 (grid 8x10x2=160)
    gemm_hl_mma<<<dim3(H_ / 128, (B_ * N_) / 128, 2), 256>>>(
        ax_hi, ax_lo, W1t_hi, W1t_lo, part, B_ * N_, H_, D_, 96);
    reduce_relu_adjmix_convert_kernel<<<(B_ * H_ + 255) / 256, 256>>>(part, 2, adj, ah_hi, ah_lo, H_);

    // GEMM2: [1280,1024]@W2 -> nodes; NC=96, S=1 (grid 16x10)
    gemm_hl_mma<<<dim3(D_ / 128, (B_ * N_) / 128, 1), 256>>>(
        ah_hi, ah_lo, W2t_hi, W2t_lo, part, B_ * N_, D_, H_, 96);
    reduce_convert_kernel<<<(B_ * N_ * D_ + 255) / 256, 256>>>(part, 1, (size_t)B_ * N_ * D_, nd_hi, nd_lo);

    // fc_g: [256,10240]@Wg; NC=960, S=8 (grid 16x2x8=256)
    gemm_hl_mma<<<dim3(D_ / 128, B_ / 128, 8), 256>>>(
        nd_hi, nd_lo, Wgt_hi, Wgt_lo, part, B_, D_, N_ * D_, 120);
    reduce_bias_convert_kernel<<<(B_ * D_ + 255) / 256, 256>>>(part, 8, B_, D_, bg, gg_hi, gg_lo);

    // fc_cls: [256,2048]@Wc; NC=192, S=16 (grid 8x2x16=256)
    gemm_hl_mma<<<dim3(NPAD_C / 128, B_ / 128, 16), 256>>>(
        gg_hi, gg_lo, Wct_hi, Wct_lo, part, B_, NPAD_C, D_, 12);
    reduce_bias_out_kernel<<<(B_ * C_ + 255) / 256, 256>>>(part, 16, NPAD_C, bc, pred_out);

    // prototypes
    class_meta_kernel<<<1, 1024>>>(tgt);
    proto_update_kernel<<<(C_ * (D_ / 4) + 255) / 256, 256>>>(x, prot, proto_out);
}

// round 4
// speedup vs baseline: 3.7130x; 1.4008x over previous
#include <cuda_runtime.h>
#include <cuda_bf16.h>
#include <cstdint>

#define B_ 256
#define N_ 5
#define D_ 2048
#define C_ 1000
#define H_ 1024
#define NPAD_C 1024
#define PROTO_M 0.999f
#define EPS_ 1e-12f

// ==================== scratch (static device globals) ====================
__device__ __nv_bfloat16 g_ax_hi[B_ * N_ * D_], g_ax_lo[B_ * N_ * D_];
__device__ __nv_bfloat16 g_ah_hi[B_ * N_ * H_], g_ah_lo[B_ * N_ * H_];
__device__ __nv_bfloat16 g_nd_hi[B_ * N_ * D_], g_nd_lo[B_ * N_ * D_];
__device__ __nv_bfloat16 g_g_hi[B_ * D_], g_g_lo[B_ * D_];
__device__ float g_part[8 * B_ * D_];   // split-K partials (max 8x256x2048 = 16MB)

__device__ float g_scale[C_];
__device__ int   g_off[C_ + 1];
__device__ int   g_idx[B_];
__device__ float g_w[B_];

// ==================== helpers ====================
__device__ __forceinline__ void split_bf16(float v, __nv_bfloat16& hi, __nv_bfloat16& lo) {
    hi = __float2bfloat16_rn(v);
    lo = __float2bfloat16_rn(v - __bfloat162float(hi));
}
__device__ __forceinline__ uint32_t smem_u32(const void* p) {
    uint32_t a;
    asm("{ .reg .u64 t; cvta.to.shared.u64 t, %1; cvt.u32.u64 %0, t; }" : "=r"(a) : "l"(p));
    return a;
}
__device__ __forceinline__ void cp_async16(uint32_t dst, const void* src) {
    asm volatile("cp.async.cg.shared.global [%0], [%1], 16;" :: "r"(dst), "l"(src));
}
__device__ __forceinline__ void cp_async16_z(uint32_t dst, const void* src, int sz) {
    asm volatile("cp.async.cg.shared.global [%0], [%1], 16, %2;" :: "r"(dst), "l"(src), "r"(sz));
}
__device__ __forceinline__ void cp_commit() { asm volatile("cp.async.commit_group;" ::: "memory"); }
__device__ __forceinline__ void cp_wait0() { asm volatile("cp.async.wait_group 0;" ::: "memory"); }

__device__ __forceinline__ void ldsm_x4(uint32_t* r, uint32_t addr) {
    asm volatile("ldmatrix.sync.aligned.m8n8.x4.shared.b16 {%0,%1,%2,%3}, [%4];"
        : "=r"(r[0]), "=r"(r[1]), "=r"(r[2]), "=r"(r[3]) : "r"(addr));
}
__device__ __forceinline__ void ldsm_x4_t(uint32_t* r, uint32_t addr) {
    asm volatile("ldmatrix.sync.aligned.m8n8.x4.trans.shared.b16 {%0,%1,%2,%3}, [%4];"
        : "=r"(r[0]), "=r"(r[1]), "=r"(r[2]), "=r"(r[3]) : "r"(addr));
}
__device__ __forceinline__ void mma16816(float* c, const uint32_t* a, uint32_t b0, uint32_t b1) {
    asm volatile(
        "mma.sync.aligned.m16n8k16.row.col.f32.bf16.bf16.f32 "
        "{%0,%1,%2,%3}, {%4,%5,%6,%7}, {%8,%9}, {%0,%1,%2,%3};"
        : "+f"(c[0]), "+f"(c[1]), "+f"(c[2]), "+f"(c[3])
        : "r"(a[0]), "r"(a[1]), "r"(a[2]), "r"(a[3]), "r"(b0), "r"(b1));
}

// ==================== adj-mix + hi/lo convert ====================
__global__ void adjmix_convert_kernel(const float* __restrict__ in,
                                      const float* __restrict__ adj,
                                      __nv_bfloat16* __restrict__ hi,
                                      __nv_bfloat16* __restrict__ lo, int F) {
    int t = blockIdx.x * blockDim.x + threadIdx.x;
    if (t >= B_ * F) return;
    int b = t / F, f = t % F;
    float xv[N_];
#pragma unroll
    for (int m = 0; m < N_; m++) xv[m] = in[((size_t)b * N_ + m) * F + f];
#pragma unroll
    for (int n = 0; n < N_; n++) {
        float s = 0.f;
#pragma unroll
        for (int m = 0; m < N_; m++) s += adj[n * N_ + m] * xv[m];
        __nv_bfloat16 h, l;
        split_bf16(s, h, l);
        hi[((size_t)b * N_ + n) * F + f] = h;
        lo[((size_t)b * N_ + n) * F + f] = l;
    }
}

// ==================== HMMA GEMM, direct f32-weight consumption ====================
// C[s] = A[M,K] @ W[K,N]  with A pre-split hi/lo bf16, W converted in-kernel.
// hi/lo split: acc = hiA*hiW + hiA*loW + loA*hiW.
// Smem layout (dynamic, double buffered):
//   Ahi [2][128 rows x 40 bf16 (80B stride)]  @ 0      (2 x 10240)
//   Alo                                        @ 20480
//   Wf32 [2][32 rows x 128 f32 (512B)]         @ 40960  (2 x 16384)
//   Bhi [2][32 rows x 136 bf16 (272B stride)]  @ 73728  (2 x 8704)
//   Blo                                        @ 91136
// total 108544 B
#define SMEM_TOTAL_GEMM 108544
template <int WM>  // 0: f32 partial to P; 1: hi/lo bf16 direct to Ohi/Olo
__global__ void __launch_bounds__(256)
gemm_direct(const __nv_bfloat16* __restrict__ A_hi, const __nv_bfloat16* __restrict__ A_lo,
            const float* __restrict__ W, float* __restrict__ P,
            __nv_bfloat16* __restrict__ Ohi, __nv_bfloat16* __restrict__ Olo,
            int M, int Npad, int Nw, int K, int NCper) {
    extern __shared__ __align__(16) uint8_t smem[];
    const uint32_t base = smem_u32(smem);
    const uint32_t oAhi = 0, oAlo = 20480, oW = 40960, oBhi = 73728, oBlo = 91136;
    const uint32_t strA = 10240, strW = 16384, strB = 8704;

    const int tid = threadIdx.x;
    const int lane = tid & 31, warp = tid >> 5;
    const int wr = warp & 3, wc = warp >> 2;     // 4x2 warp grid, warp tile 32x64
    const int row0 = blockIdx.y * 128, col0 = blockIdx.x * 128;
    const int c0 = blockIdx.z * NCper;

    // cp.async A slots: idx = tid + i*256 -> row idx>>2, 16B-quad idx&3
    const int ar0 = tid >> 2, aq0 = tid & 3;
    const int ar1 = (tid + 256) >> 2, aq1 = (tid + 256) & 3;
    // cp.async W slots: idx = tid + i*256 -> k idx>>5, quad idx&31 (guarded by Nw)
    int wk[4], wq[4], wsz[4];
#pragma unroll
    for (int i = 0; i < 4; i++) {
        int idx = tid + i * 256;
        wk[i] = idx >> 5; wq[i] = idx & 31;
        int v = (Nw - (col0 + wq[i] * 4)) * 4;
        wsz[i] = v < 0 ? 0 : (v > 16 ? 16 : v);
    }

    // ldmatrix lane selectors
    const int selRow = (lane & 7) + ((lane >> 3) & 1) * 8;  // 0..15
    const int selHi = (lane >> 4) & 1;
    const uint32_t aOff = (uint32_t)((wr * 32 + selRow) * 80 + selHi * 16);
    const uint32_t bOff = (uint32_t)(selRow * 272 + wc * 128 + selHi * 16);

    float acc[2][8][4] = {};

    auto stage = [&](int c, int buf) {
        int kk = c * 32;
        uint32_t da = base + oAhi + buf * strA;
        uint32_t dl = base + oAlo + buf * strA;
        uint32_t dw = base + oW + buf * strW;
        cp_async16(da + ar0 * 80 + aq0 * 16, A_hi + (size_t)(row0 + ar0) * K + kk + aq0 * 8);
        cp_async16(da + ar1 * 80 + aq1 * 16, A_hi + (size_t)(row0 + ar1) * K + kk + aq1 * 8);
        cp_async16(dl + ar0 * 80 + aq0 * 16, A_lo + (size_t)(row0 + ar0) * K + kk + aq0 * 8);
        cp_async16(dl + ar1 * 80 + aq1 * 16, A_lo + (size_t)(row0 + ar1) * K + kk + aq1 * 8);
#pragma unroll
        for (int i = 0; i < 4; i++) {
            const float* src = wsz[i] ? (W + (size_t)(kk + wk[i]) * Nw + col0 + wq[i] * 4) : W;
            cp_async16_z(dw + wk[i] * 512 + wq[i] * 16, src, wsz[i]);
        }
    };

    stage(c0, 0);
    cp_commit();

    for (int li = 0; li < NCper; li++) {
        const int buf = li & 1;
        cp_wait0();
        __syncthreads();
        if (li + 1 < NCper) { stage(c0 + li + 1, buf ^ 1); cp_commit(); }

        // convert W f32 tile -> bf16 hi/lo (each thread: 16 consecutive f32 in one k-row)
        {
            const float4* wp = reinterpret_cast<const float4*>(smem + oW + buf * strW + tid * 64);
            float fv[16];
#pragma unroll
            for (int i = 0; i < 4; i++) {
                float4 v = wp[i];
                fv[4 * i] = v.x; fv[4 * i + 1] = v.y; fv[4 * i + 2] = v.z; fv[4 * i + 3] = v.w;
            }
            uint32_t hw[8], lw[8];
#pragma unroll
            for (int i = 0; i < 8; i++) {
                __nv_bfloat16 h0, l0, h1, l1;
                split_bf16(fv[2 * i], h0, l0);
                split_bf16(fv[2 * i + 1], h1, l1);
                __nv_bfloat162 hh; hh.x = h0; hh.y = h1;
                __nv_bfloat162 ll; ll.x = l0; ll.y = l1;
                hw[i] = *reinterpret_cast<uint32_t*>(&hh);
                lw[i] = *reinterpret_cast<uint32_t*>(&ll);
            }
            uint32_t wb = (uint32_t)((tid >> 3) * 272 + (tid & 7) * 32);
            uint4* oh = reinterpret_cast<uint4*>(smem + oBhi + buf * strB + wb);
            uint4* ol = reinterpret_cast<uint4*>(smem + oBlo + buf * strB + wb);
            oh[0] = make_uint4(hw[0], hw[1], hw[2], hw[3]);
            oh[1] = make_uint4(hw[4], hw[5], hw[6], hw[7]);
            ol[0] = make_uint4(lw[0], lw[1], lw[2], lw[3]);
            ol[1] = make_uint4(lw[4], lw[5], lw[6], lw[7]);
        }
        __syncthreads();

        const uint32_t ah = base + oAhi + buf * strA, al = base + oAlo + buf * strA;
        const uint32_t bh = base + oBhi + buf * strB, bl = base + oBlo + buf * strB;
#pragma unroll
        for (int ks = 0; ks < 2; ks++) {
            uint32_t fah[2][4], fal[2][4], fbh[4][4], fbl[4][4];
            ldsm_x4(fah[0], ah + aOff + ks * 32);
            ldsm_x4(fah[1], ah + aOff + 1280 + ks * 32);
            ldsm_x4(fal[0], al + aOff + ks * 32);
            ldsm_x4(fal[1], al + aOff + 1280 + ks * 32);
#pragma unroll
            for (int p = 0; p < 4; p++) {
                ldsm_x4_t(fbh[p], bh + bOff + ks * 4352 + p * 32);
                ldsm_x4_t(fbl[p], bl + bOff + ks * 4352 + p * 32);
            }
            // 3 passes, 16 independent acc targets each (no RAW chains)
#pragma unroll
            for (int mi = 0; mi < 2; mi++)
#pragma unroll
                for (int p = 0; p < 4; p++) {
                    mma16816(acc[mi][2 * p], fah[mi], fbh[p][0], fbh[p][1]);
                    mma16816(acc[mi][2 * p + 1], fah[mi], fbh[p][2], fbh[p][3]);
                }
#pragma unroll
            for (int mi = 0; mi < 2; mi++)
#pragma unroll
                for (int p = 0; p < 4; p++) {
                    mma16816(acc[mi][2 * p], fah[mi], fbl[p][0], fbl[p][1]);
                    mma16816(acc[mi][2 * p + 1], fah[mi], fbl[p][2], fbl[p][3]);
                }
#pragma unroll
            for (int mi = 0; mi < 2; mi++)
#pragma unroll
                for (int p = 0; p < 4; p++) {
                    mma16816(acc[mi][2 * p], fal[mi], fbh[p][0], fbh[p][1]);
                    mma16816(acc[mi][2 * p + 1], fal[mi], fbh[p][2], fbh[p][3]);
                }
        }
    }

    // epilogue
    const int g = lane >> 2, tg = lane & 3;
    if (WM == 0) {
        size_t zb = (size_t)blockIdx.z * M * Npad;
#pragma unroll
        for (int mi = 0; mi < 2; mi++)
#pragma unroll
            for (int half = 0; half < 2; half++) {
                int r = row0 + wr * 32 + mi * 16 + g + half * 8;
                float* rowp = P + zb + (size_t)r * Npad + col0 + wc * 64;
#pragma unroll
                for (int ni = 0; ni < 8; ni++)
                    *reinterpret_cast<float2*>(rowp + ni * 8 + tg * 2) =
                        make_float2(acc[mi][ni][half * 2], acc[mi][ni][half * 2 + 1]);
            }
    } else {
#pragma unroll
        for (int mi = 0; mi < 2; mi++)
#pragma unroll
            for (int half = 0; half < 2; half++) {
                int r = row0 + wr * 32 + mi * 16 + g + half * 8;
                size_t rb = (size_t)r * Npad + col0 + wc * 64;
#pragma unroll
                for (int ni = 0; ni < 8; ni++) {
                    float v0 = acc[mi][ni][half * 2], v1 = acc[mi][ni][half * 2 + 1];
                    __nv_bfloat16 h0, l0, h1, l1;
                    split_bf16(v0, h0, l0);
                    split_bf16(v1, h1, l1);
                    __nv_bfloat162 hh; hh.x = h0; hh.y = h1;
                    __nv_bfloat162 ll; ll.x = l0; ll.y = l1;
                    *reinterpret_cast<__nv_bfloat162*>(Ohi + rb + ni * 8 + tg * 2) = hh;
                    *reinterpret_cast<__nv_bfloat162*>(Olo + rb + ni * 8 + tg * 2) = ll;
                }
            }
    }
}

// ==================== reduce epilogues ====================
__global__ void reduce_relu_adjmix_convert_kernel(const float* __restrict__ P, int S,
                                                  const float* __restrict__ adj,
                                                  __nv_bfloat16* __restrict__ hi,
                                                  __nv_bfloat16* __restrict__ lo, int F) {
    int t = blockIdx.x * blockDim.x + threadIdx.x;
    if (t >= B_ * F) return;
    int b = t / F, f = t % F;
    float hv[N_];
#pragma unroll
    for (int m = 0; m < N_; m++) {
        float s = 0.f;
        for (int j = 0; j < S; j++)
            s += P[(size_t)j * (B_ * N_ * F) + ((size_t)b * N_ + m) * F + f];
        hv[m] = fmaxf(s, 0.f);
    }
#pragma unroll
    for (int n = 0; n < N_; n++) {
        float s = 0.f;
#pragma unroll
        for (int m = 0; m < N_; m++) s += adj[n * N_ + m] * hv[m];
        __nv_bfloat16 h, l;
        split_bf16(s, h, l);
        hi[((size_t)b * N_ + n) * F + f] = h;
        lo[((size_t)b * N_ + n) * F + f] = l;
    }
}

__global__ void reduce_bias_convert_kernel(const float* __restrict__ P, int S, int M, int N,
                                           const float* __restrict__ bias,
                                           __nv_bfloat16* __restrict__ hi,
                                           __nv_bfloat16* __restrict__ lo) {
    int t = blockIdx.x * blockDim.x + threadIdx.x;
    if (t >= M * N) return;
    float s = bias[t % N];
    for (int j = 0; j < S; j++) s += P[(size_t)j * M * N + t];
    __nv_bfloat16 h, l;
    split_bf16(s, h, l);
    hi[t] = h;
    lo[t] = l;
}

__global__ void reduce_bias_out_kernel(const float* __restrict__ P, int S, int Npad,
                                       const float* __restrict__ bias,
                                       float* __restrict__ out) {
    int t = blockIdx.x * blockDim.x + threadIdx.x;
    if (t >= B_ * C_) return;
    int b = t / C_, n = t % C_;
    float s = bias[n];
    for (int j = 0; j < S; j++) s += P[(size_t)j * B_ * Npad + (size_t)b * Npad + n];
    out[t] = s;
}

// ==================== prototype EMA (closed form), parallel metadata ====================
__global__ void class_meta_kernel(const int* __restrict__ target) {  // 1 block, 1024 thr
    __shared__ int cnt[1024];
    __shared__ int scan[1024];
    __shared__ int t_s[B_];
    __shared__ int rank_s[B_];
    int tid = threadIdx.x;
    cnt[tid] = 0;
    __syncthreads();
    if (tid < B_) t_s[tid] = target[tid];
    __syncthreads();
    if (tid < B_) {
        int c = t_s[tid], r = 0;
        for (int j = 0; j < tid; j++) r += (t_s[j] == c) ? 1 : 0;
        rank_s[tid] = r;
        atomicAdd(&cnt[c], 1);
    }
    __syncthreads();
    if (tid < C_) g_scale[tid] = powf(PROTO_M, (float)cnt[tid]);
    scan[tid] = cnt[tid];
    __syncthreads();
    for (int ofs = 1; ofs < 1024; ofs <<= 1) {
        int v = (tid >= ofs) ? scan[tid - ofs] : 0;
        __syncthreads();
        scan[tid] += v;
        __syncthreads();
    }
    if (tid < C_) g_off[tid] = scan[tid] - cnt[tid];
    if (tid == 0) g_off[C_] = B_;
    __syncthreads();
    if (tid < B_) {
        int c = t_s[tid];
        int p = (scan[c] - cnt[c]) + rank_s[tid];
        g_idx[p] = tid;
        g_w[p] = (1.0f - PROTO_M) * powf(PROTO_M, (float)(cnt[c] - 1 - rank_s[tid]));
    }
}

__global__ void proto_update_kernel(const float* __restrict__ x,
                                    const float* __restrict__ protos,
                                    float* __restrict__ out) {
    int t = blockIdx.x * blockDim.x + threadIdx.x;
    const int D4 = D_ / 4;
    if (t >= C_ * D4) return;
    int c = t / D4, d4 = t % D4;
    float s = g_scale[c];
    float4 v[N_];
#pragma unroll
    for (int n = 0; n < N_; n++) {
        float4 p = *reinterpret_cast<const float4*>(protos + ((size_t)c * N_ + n) * D_ + d4 * 4);
        v[n] = make_float4(p.x * s, p.y * s, p.z * s, p.w * s);
    }
    int e = g_off[c + 1];
    for (int j = g_off[c]; j < e; j++) {
        int i = g_idx[j];
        float w = g_w[j];
#pragma unroll
        for (int n = 0; n < N_; n++) {
            float4 xv = *reinterpret_cast<const float4*>(x + ((size_t)i * N_ + n) * D_ + d4 * 4);
            v[n].x += w * xv.x; v[n].y += w * xv.y;
            v[n].z += w * xv.z; v[n].w += w * xv.w;
        }
    }
    float4 nrm4 = make_float4(0.f, 0.f, 0.f, 0.f);
#pragma unroll
    for (int n = 0; n < N_; n++) {
        nrm4.x += v[n].x * v[n].x; nrm4.y += v[n].y * v[n].y;
        nrm4.z += v[n].z * v[n].z; nrm4.w += v[n].w * v[n].w;
    }
    float4 inv = make_float4(1.f / fmaxf(sqrtf(nrm4.x), EPS_), 1.f / fmaxf(sqrtf(nrm4.y), EPS_),
                             1.f / fmaxf(sqrtf(nrm4.z), EPS_), 1.f / fmaxf(sqrtf(nrm4.w), EPS_));
#pragma unroll
    for (int n = 0; n < N_; n++) {
        float4 o = make_float4(v[n].x * inv.x, v[n].y * inv.y, v[n].z * inv.z, v[n].w * inv.w);
        *reinterpret_cast<float4*>(out + ((size_t)c * N_ + n) * D_ + d4 * 4) = o;
    }
}

// ==================== launch ====================
extern "C" void kernel_launch(void* const* d_in, const int* in_sizes, int n_in,
                              void* d_out, int out_size) {
    const float* x    = (const float*)d_in[0];
    const int*   tgt  = (const int*)d_in[1];
    const float* prot = (const float*)d_in[2];
    const float* adj  = (const float*)d_in[3];
    const float* W1   = (const float*)d_in[4];
    const float* W2   = (const float*)d_in[5];
    const float* Wg   = (const float*)d_in[6];
    const float* bg   = (const float*)d_in[7];
    const float* Wc   = (const float*)d_in[8];
    const float* bc   = (const float*)d_in[9];

    float* pred_out  = (float*)d_out;
    float* proto_out = (float*)d_out + (size_t)B_ * C_;

    __nv_bfloat16 *ax_hi, *ax_lo, *ah_hi, *ah_lo, *nd_hi, *nd_lo, *gg_hi, *gg_lo;
    float* part;
    cudaGetSymbolAddress((void**)&ax_hi, g_ax_hi);   cudaGetSymbolAddress((void**)&ax_lo, g_ax_lo);
    cudaGetSymbolAddress((void**)&ah_hi, g_ah_hi);   cudaGetSymbolAddress((void**)&ah_lo, g_ah_lo);
    cudaGetSymbolAddress((void**)&nd_hi, g_nd_hi);   cudaGetSymbolAddress((void**)&nd_lo, g_nd_lo);
    cudaGetSymbolAddress((void**)&gg_hi, g_g_hi);    cudaGetSymbolAddress((void**)&gg_lo, g_g_lo);
    cudaGetSymbolAddress((void**)&part, g_part);

    cudaFuncSetAttribute(gemm_direct<0>, cudaFuncAttributeMaxDynamicSharedMemorySize, SMEM_TOTAL_GEMM);
    cudaFuncSetAttribute(gemm_direct<1>, cudaFuncAttributeMaxDynamicSharedMemorySize, SMEM_TOTAL_GEMM);

    // ax = adj @ x (+ hi/lo convert)
    adjmix_convert_kernel<<<(B_ * D_ + 255) / 256, 256>>>(x, adj, ax_hi, ax_lo, D_);

    // GEMM1: [1280,2048]@W1[2048,1024], S=1, 64 chunks, grid 8x10 -> f32 part
    gemm_direct<0><<<dim3(H_ / 128, (B_ * N_) / 128, 1), 256, SMEM_TOTAL_GEMM>>>(
        ax_hi, ax_lo, W1, part, nullptr, nullptr, B_ * N_, H_, H_, D_, 64);
    reduce_relu_adjmix_convert_kernel<<<(B_ * H_ + 255) / 256, 256>>>(part, 1, adj, ah_hi, ah_lo, H_);

    // GEMM2: [1280,1024]@W2[1024,2048], S=1, 32 chunks, grid 16x10 -> hi/lo direct
    gemm_direct<1><<<dim3(D_ / 128, (B_ * N_) / 128, 1), 256, SMEM_TOTAL_GEMM>>>(
        ah_hi, ah_lo, W2, nullptr, nd_hi, nd_lo, B_ * N_, D_, D_, H_, 32);

    // fc_g: [256,10240]@Wg[10240,2048], S=4 (grid 16x2x4=128), 80 chunks/split
    gemm_direct<0><<<dim3(D_ / 128, B_ / 128, 4), 256, SMEM_TOTAL_GEMM>>>(
        nd_hi, nd_lo, Wg, part, nullptr, nullptr, B_, D_, D_, N_ * D_, 80);
    reduce_bias_convert_kernel<<<(B_ * D_ + 255) / 256, 256>>>(part, 4, B_, D_, bg, gg_hi, gg_lo);

    // fc_cls: [256,2048]@Wc[2048,1000->pad 1024], S=8 (grid 8x2x8=128), 8 chunks/split
    gemm_direct<0><<<dim3(NPAD_C / 128, B_ / 128, 8), 256, SMEM_TOTAL_GEMM>>>(
        gg_hi, gg_lo, Wc, part, nullptr, nullptr, B_, NPAD_C, C_, D_, 8);
    reduce_bias_out_kernel<<<(B_ * C_ + 255) / 256, 256>>>(part, 8, NPAD_C, bc, pred_out);

    // prototypes
    class_meta_kernel<<<1, 1024>>>(tgt);
    proto_update_kernel<<<(C_ * (D_ / 4) + 255) / 256, 256>>>(x, prot, proto_out);
}

// round 5
// speedup vs baseline: 4.0104x; 1.0801x over previous
#include <cuda_runtime.h>
#include <cuda_bf16.h>
#include <cstdint>

#define B_ 256
#define N_ 5
#define D_ 2048
#define C_ 1000
#define H_ 1024
#define NPAD_C 1024
#define PROTO_M 0.999f
#define EPS_ 1e-12f

// ==================== scratch (static device globals) ====================
__device__ __nv_bfloat16 g_ax_hi[B_ * N_ * D_], g_ax_lo[B_ * N_ * D_];
__device__ __nv_bfloat16 g_ah_hi[B_ * N_ * H_], g_ah_lo[B_ * N_ * H_];
__device__ __nv_bfloat16 g_nd_hi[B_ * N_ * D_], g_nd_lo[B_ * N_ * D_];
__device__ __nv_bfloat16 g_g_hi[B_ * D_], g_g_lo[B_ * D_];
__device__ float g_part[8 * B_ * D_];   // split-K partials (max 8x256x2048 = 16MB)

__device__ float g_scale[C_];
__device__ int   g_off[C_ + 1];
__device__ int   g_idx[B_];
__device__ float g_w[B_];

// ==================== helpers ====================
__device__ __forceinline__ void split_bf16(float v, __nv_bfloat16& hi, __nv_bfloat16& lo) {
    hi = __float2bfloat16_rn(v);
    lo = __float2bfloat16_rn(v - __bfloat162float(hi));
}
__device__ __forceinline__ uint32_t smem_u32(const void* p) {
    uint32_t a;
    asm("{ .reg .u64 t; cvta.to.shared.u64 t, %1; cvt.u32.u64 %0, t; }" : "=r"(a) : "l"(p));
    return a;
}
__device__ __forceinline__ void cp_async16(uint32_t dst, const void* src) {
    asm volatile("cp.async.cg.shared.global [%0], [%1], 16;" :: "r"(dst), "l"(src));
}
__device__ __forceinline__ void cp_async16_z(uint32_t dst, const void* src, int sz) {
    asm volatile("cp.async.cg.shared.global [%0], [%1], 16, %2;" :: "r"(dst), "l"(src), "r"(sz));
}
__device__ __forceinline__ void cp_commit() { asm volatile("cp.async.commit_group;" ::: "memory"); }
__device__ __forceinline__ void cp_wait0() { asm volatile("cp.async.wait_group 0;" ::: "memory"); }

__device__ __forceinline__ void ldsm_x4(uint32_t* r, uint32_t addr) {
    asm volatile("ldmatrix.sync.aligned.m8n8.x4.shared.b16 {%0,%1,%2,%3}, [%4];"
        : "=r"(r[0]), "=r"(r[1]), "=r"(r[2]), "=r"(r[3]) : "r"(addr));
}
__device__ __forceinline__ void ldsm_x4_t(uint32_t* r, uint32_t addr) {
    asm volatile("ldmatrix.sync.aligned.m8n8.x4.trans.shared.b16 {%0,%1,%2,%3}, [%4];"
        : "=r"(r[0]), "=r"(r[1]), "=r"(r[2]), "=r"(r[3]) : "r"(addr));
}
__device__ __forceinline__ void mma16816(float* c, const uint32_t* a, uint32_t b0, uint32_t b1) {
    asm volatile(
        "mma.sync.aligned.m16n8k16.row.col.f32.bf16.bf16.f32 "
        "{%0,%1,%2,%3}, {%4,%5,%6,%7}, {%8,%9}, {%0,%1,%2,%3};"
        : "+f"(c[0]), "+f"(c[1]), "+f"(c[2]), "+f"(c[3])
        : "r"(a[0]), "r"(a[1]), "r"(a[2]), "r"(a[3]), "r"(b0), "r"(b1));
}

// ==================== adj-mix + hi/lo convert ====================
__global__ void adjmix_convert_kernel(const float* __restrict__ in,
                                      const float* __restrict__ adj,
                                      __nv_bfloat16* __restrict__ hi,
                                      __nv_bfloat16* __restrict__ lo, int F) {
    int t = blockIdx.x * blockDim.x + threadIdx.x;
    if (t >= B_ * F) return;
    int b = t / F, f = t % F;
    float xv[N_];
#pragma unroll
    for (int m = 0; m < N_; m++) xv[m] = in[((size_t)b * N_ + m) * F + f];
#pragma unroll
    for (int n = 0; n < N_; n++) {
        float s = 0.f;
#pragma unroll
        for (int m = 0; m < N_; m++) s += adj[n * N_ + m] * xv[m];
        __nv_bfloat16 h, l;
        split_bf16(s, h, l);
        hi[((size_t)b * N_ + n) * F + f] = h;
        lo[((size_t)b * N_ + n) * F + f] = l;
    }
}

// ==================== HMMA GEMM, direct f32-weight consumption ====================
// C[s] = A[M,K] @ W[K,N]  with A pre-split hi/lo bf16, W converted in-kernel.
// hi/lo split: acc = hiA*hiW + hiA*loW + loA*hiW.
// Smem (dynamic, double buffered): Ahi@0, Alo@20480 (80B row stride),
// Wf32@40960 (512B rows), Bhi@73728, Blo@91136 (272B rows). Total 108544 B.
#define SMEM_TOTAL_GEMM 108544
template <int WM>  // 0: f32 partial to P; 1: hi/lo bf16 direct to Ohi/Olo
__global__ void __launch_bounds__(256, 2)
gemm_direct(const __nv_bfloat16* __restrict__ A_hi, const __nv_bfloat16* __restrict__ A_lo,
            const float* __restrict__ W, float* __restrict__ P,
            __nv_bfloat16* __restrict__ Ohi, __nv_bfloat16* __restrict__ Olo,
            int M, int Npad, int Nw, int K, int NCper) {
    extern __shared__ __align__(16) uint8_t smem[];
    const uint32_t base = smem_u32(smem);
    const uint32_t oAhi = 0, oAlo = 20480, oW = 40960, oBhi = 73728, oBlo = 91136;
    const uint32_t strA = 10240, strW = 16384, strB = 8704;

    const int tid = threadIdx.x;
    const int lane = tid & 31, warp = tid >> 5;
    const int wr = warp & 3, wc = warp >> 2;     // 4x2 warp grid, warp tile 32x64
    const int row0 = blockIdx.y * 128, col0 = blockIdx.x * 128;
    const int c0 = blockIdx.z * NCper;

    const int ar0 = tid >> 2, aq0 = tid & 3;
    const int ar1 = (tid + 256) >> 2, aq1 = (tid + 256) & 3;
    int wk[4], wq[4], wsz[4];
#pragma unroll
    for (int i = 0; i < 4; i++) {
        int idx = tid + i * 256;
        wk[i] = idx >> 5; wq[i] = idx & 31;
        int v = (Nw - (col0 + wq[i] * 4)) * 4;
        wsz[i] = v < 0 ? 0 : (v > 16 ? 16 : v);
    }

    const int selRow = (lane & 7) + ((lane >> 3) & 1) * 8;
    const int selHi = (lane >> 4) & 1;
    const uint32_t aOff = (uint32_t)((wr * 32 + selRow) * 80 + selHi * 16);
    const uint32_t bOff = (uint32_t)(selRow * 272 + wc * 128 + selHi * 16);

    float acc[2][8][4] = {};

    auto stage = [&](int c, int buf) {
        int kk = c * 32;
        uint32_t da = base + oAhi + buf * strA;
        uint32_t dl = base + oAlo + buf * strA;
        uint32_t dw = base + oW + buf * strW;
        cp_async16(da + ar0 * 80 + aq0 * 16, A_hi + (size_t)(row0 + ar0) * K + kk + aq0 * 8);
        cp_async16(da + ar1 * 80 + aq1 * 16, A_hi + (size_t)(row0 + ar1) * K + kk + aq1 * 8);
        cp_async16(dl + ar0 * 80 + aq0 * 16, A_lo + (size_t)(row0 + ar0) * K + kk + aq0 * 8);
        cp_async16(dl + ar1 * 80 + aq1 * 16, A_lo + (size_t)(row0 + ar1) * K + kk + aq1 * 8);
#pragma unroll
        for (int i = 0; i < 4; i++) {
            const float* src = wsz[i] ? (W + (size_t)(kk + wk[i]) * Nw + col0 + wq[i] * 4) : W;
            cp_async16_z(dw + wk[i] * 512 + wq[i] * 16, src, wsz[i]);
        }
    };

    stage(c0, 0);
    cp_commit();

    for (int li = 0; li < NCper; li++) {
        const int buf = li & 1;
        cp_wait0();
        __syncthreads();
        if (li + 1 < NCper) { stage(c0 + li + 1, buf ^ 1); cp_commit(); }

        // convert W f32 tile -> bf16 hi/lo
        {
            const float4* wp = reinterpret_cast<const float4*>(smem + oW + buf * strW + tid * 64);
            uint32_t hw[8], lw[8];
#pragma unroll
            for (int i = 0; i < 4; i++) {
                float4 v = wp[i];
                __nv_bfloat16 h0, l0, h1, l1;
                split_bf16(v.x, h0, l0); split_bf16(v.y, h1, l1);
                __nv_bfloat162 hh; hh.x = h0; hh.y = h1;
                __nv_bfloat162 ll; ll.x = l0; ll.y = l1;
                hw[2 * i] = *reinterpret_cast<uint32_t*>(&hh);
                lw[2 * i] = *reinterpret_cast<uint32_t*>(&ll);
                split_bf16(v.z, h0, l0); split_bf16(v.w, h1, l1);
                hh.x = h0; hh.y = h1; ll.x = l0; ll.y = l1;
                hw[2 * i + 1] = *reinterpret_cast<uint32_t*>(&hh);
                lw[2 * i + 1] = *reinterpret_cast<uint32_t*>(&ll);
            }
            uint32_t wb = (uint32_t)((tid >> 3) * 272 + (tid & 7) * 32);
            uint4* oh = reinterpret_cast<uint4*>(smem + oBhi + buf * strB + wb);
            uint4* ol = reinterpret_cast<uint4*>(smem + oBlo + buf * strB + wb);
            oh[0] = make_uint4(hw[0], hw[1], hw[2], hw[3]);
            oh[1] = make_uint4(hw[4], hw[5], hw[6], hw[7]);
            ol[0] = make_uint4(lw[0], lw[1], lw[2], lw[3]);
            ol[1] = make_uint4(lw[4], lw[5], lw[6], lw[7]);
        }
        __syncthreads();

        const uint32_t ah = base + oAhi + buf * strA, al = base + oAlo + buf * strA;
        const uint32_t bh = base + oBhi + buf * strB, bl = base + oBlo + buf * strB;
#pragma unroll
        for (int ks = 0; ks < 2; ks++) {
            uint32_t fa[2][4], fb1[4][4], fb2[4][4];
            // pass 1: hiA * hiW
            ldsm_x4(fa[0], ah + aOff + ks * 32);
            ldsm_x4(fa[1], ah + aOff + 1280 + ks * 32);
#pragma unroll
            for (int p = 0; p < 4; p++) ldsm_x4_t(fb1[p], bh + bOff + ks * 4352 + p * 32);
#pragma unroll
            for (int mi = 0; mi < 2; mi++)
#pragma unroll
                for (int p = 0; p < 4; p++) {
                    mma16816(acc[mi][2 * p], fa[mi], fb1[p][0], fb1[p][1]);
                    mma16816(acc[mi][2 * p + 1], fa[mi], fb1[p][2], fb1[p][3]);
                }
            // pass 2: hiA * loW
#pragma unroll
            for (int p = 0; p < 4; p++) ldsm_x4_t(fb2[p], bl + bOff + ks * 4352 + p * 32);
#pragma unroll
            for (int mi = 0; mi < 2; mi++)
#pragma unroll
                for (int p = 0; p < 4; p++) {
                    mma16816(acc[mi][2 * p], fa[mi], fb2[p][0], fb2[p][1]);
                    mma16816(acc[mi][2 * p + 1], fa[mi], fb2[p][2], fb2[p][3]);
                }
            // pass 3: loA * hiW (fa overwritten, fb2 dead)
            ldsm_x4(fa[0], al + aOff + ks * 32);
            ldsm_x4(fa[1], al + aOff + 1280 + ks * 32);
#pragma unroll
            for (int mi = 0; mi < 2; mi++)
#pragma unroll
                for (int p = 0; p < 4; p++) {
                    mma16816(acc[mi][2 * p], fa[mi], fb1[p][0], fb1[p][1]);
                    mma16816(acc[mi][2 * p + 1], fa[mi], fb1[p][2], fb1[p][3]);
                }
        }
    }

    // epilogue
    const int g = lane >> 2, tg = lane & 3;
    if (WM == 0) {
        size_t zb = (size_t)blockIdx.z * M * Npad;
#pragma unroll
        for (int mi = 0; mi < 2; mi++)
#pragma unroll
            for (int half = 0; half < 2; half++) {
                int r = row0 + wr * 32 + mi * 16 + g + half * 8;
                float* rowp = P + zb + (size_t)r * Npad + col0 + wc * 64;
#pragma unroll
                for (int ni = 0; ni < 8; ni++)
                    *reinterpret_cast<float2*>(rowp + ni * 8 + tg * 2) =
                        make_float2(acc[mi][ni][half * 2], acc[mi][ni][half * 2 + 1]);
            }
    } else {
#pragma unroll
        for (int mi = 0; mi < 2; mi++)
#pragma unroll
            for (int half = 0; half < 2; half++) {
                int r = row0 + wr * 32 + mi * 16 + g + half * 8;
                size_t rb = (size_t)r * Npad + col0 + wc * 64;
#pragma unroll
                for (int ni = 0; ni < 8; ni++) {
                    __nv_bfloat16 h0, l0, h1, l1;
                    split_bf16(acc[mi][ni][half * 2], h0, l0);
                    split_bf16(acc[mi][ni][half * 2 + 1], h1, l1);
                    __nv_bfloat162 hh; hh.x = h0; hh.y = h1;
                    __nv_bfloat162 ll; ll.x = l0; ll.y = l1;
                    *reinterpret_cast<__nv_bfloat162*>(Ohi + rb + ni * 8 + tg * 2) = hh;
                    *reinterpret_cast<__nv_bfloat162*>(Olo + rb + ni * 8 + tg * 2) = ll;
                }
            }
    }
}

// ==================== reduce epilogues ====================
__global__ void reduce_relu_adjmix_convert_kernel(const float* __restrict__ P, int S,
                                                  const float* __restrict__ adj,
                                                  __nv_bfloat16* __restrict__ hi,
                                                  __nv_bfloat16* __restrict__ lo, int F) {
    int t = blockIdx.x * blockDim.x + threadIdx.x;
    if (t >= B_ * F) return;
    int b = t / F, f = t % F;
    float hv[N_];
#pragma unroll
    for (int m = 0; m < N_; m++) {
        float s = 0.f;
        for (int j = 0; j < S; j++)
            s += P[(size_t)j * (B_ * N_ * F) + ((size_t)b * N_ + m) * F + f];
        hv[m] = fmaxf(s, 0.f);
    }
#pragma unroll
    for (int n = 0; n < N_; n++) {
        float s = 0.f;
#pragma unroll
        for (int m = 0; m < N_; m++) s += adj[n * N_ + m] * hv[m];
        __nv_bfloat16 h, l;
        split_bf16(s, h, l);
        hi[((size_t)b * N_ + n) * F + f] = h;
        lo[((size_t)b * N_ + n) * F + f] = l;
    }
}

__global__ void reduce_bias_convert_kernel(const float* __restrict__ P, int S, int M, int N,
                                           const float* __restrict__ bias,
                                           __nv_bfloat16* __restrict__ hi,
                                           __nv_bfloat16* __restrict__ lo) {
    int t = blockIdx.x * blockDim.x + threadIdx.x;
    if (t >= M * N) return;
    float s = bias[t % N];
    for (int j = 0; j < S; j++) s += P[(size_t)j * M * N + t];
    __nv_bfloat16 h, l;
    split_bf16(s, h, l);
    hi[t] = h;
    lo[t] = l;
}

__global__ void reduce_bias_out_kernel(const float* __restrict__ P, int S, int Npad,
                                       const float* __restrict__ bias,
                                       float* __restrict__ out) {
    int t = blockIdx.x * blockDim.x + threadIdx.x;
    if (t >= B_ * C_) return;
    int b = t / C_, n = t % C_;
    float s = bias[n];
    for (int j = 0; j < S; j++) s += P[(size_t)j * B_ * Npad + (size_t)b * Npad + n];
    out[t] = s;
}

// ==================== prototype EMA (closed form), parallel metadata ====================
__global__ void class_meta_kernel(const int* __restrict__ target) {  // 1 block, 1024 thr
    __shared__ int cnt[1024];
    __shared__ int scan[1024];
    __shared__ int t_s[B_];
    __shared__ int rank_s[B_];
    int tid = threadIdx.x;
    cnt[tid] = 0;
    __syncthreads();
    if (tid < B_) t_s[tid] = target[tid];
    __syncthreads();
    if (tid < B_) {
        int c = t_s[tid], r = 0;
        for (int j = 0; j < tid; j++) r += (t_s[j] == c) ? 1 : 0;
        rank_s[tid] = r;
        atomicAdd(&cnt[c], 1);
    }
    __syncthreads();
    if (tid < C_) g_scale[tid] = powf(PROTO_M, (float)cnt[tid]);
    scan[tid] = cnt[tid];
    __syncthreads();
    for (int ofs = 1; ofs < 1024; ofs <<= 1) {
        int v = (tid >= ofs) ? scan[tid - ofs] : 0;
        __syncthreads();
        scan[tid] += v;
        __syncthreads();
    }
    if (tid < C_) g_off[tid] = scan[tid] - cnt[tid];
    if (tid == 0) g_off[C_] = B_;
    __syncthreads();
    if (tid < B_) {
        int c = t_s[tid];
        int p = (scan[c] - cnt[c]) + rank_s[tid];
        g_idx[p] = tid;
        g_w[p] = (1.0f - PROTO_M) * powf(PROTO_M, (float)(cnt[c] - 1 - rank_s[tid]));
    }
}

__global__ void proto_update_kernel(const float* __restrict__ x,
                                    const float* __restrict__ protos,
                                    float* __restrict__ out) {
    int t = blockIdx.x * blockDim.x + threadIdx.x;
    const int D4 = D_ / 4;
    if (t >= C_ * D4) return;
    int c = t / D4, d4 = t % D4;
    float s = g_scale[c];
    float4 v[N_];
#pragma unroll
    for (int n = 0; n < N_; n++) {
        float4 p = *reinterpret_cast<const float4*>(protos + ((size_t)c * N_ + n) * D_ + d4 * 4);
        v[n] = make_float4(p.x * s, p.y * s, p.z * s, p.w * s);
    }
    int e = g_off[c + 1];
    for (int j = g_off[c]; j < e; j++) {
        int i = g_idx[j];
        float w = g_w[j];
#pragma unroll
        for (int n = 0; n < N_; n++) {
            float4 xv = *reinterpret_cast<const float4*>(x + ((size_t)i * N_ + n) * D_ + d4 * 4);
            v[n].x += w * xv.x; v[n].y += w * xv.y;
            v[n].z += w * xv.z; v[n].w += w * xv.w;
        }
    }
    float4 nrm4 = make_float4(0.f, 0.f, 0.f, 0.f);
#pragma unroll
    for (int n = 0; n < N_; n++) {
        nrm4.x += v[n].x * v[n].x; nrm4.y += v[n].y * v[n].y;
        nrm4.z += v[n].z * v[n].z; nrm4.w += v[n].w * v[n].w;
    }
    float4 inv = make_float4(1.f / fmaxf(sqrtf(nrm4.x), EPS_), 1.f / fmaxf(sqrtf(nrm4.y), EPS_),
                             1.f / fmaxf(sqrtf(nrm4.z), EPS_), 1.f / fmaxf(sqrtf(nrm4.w), EPS_));
#pragma unroll
    for (int n = 0; n < N_; n++) {
        float4 o = make_float4(v[n].x * inv.x, v[n].y * inv.y, v[n].z * inv.z, v[n].w * inv.w);
        *reinterpret_cast<float4*>(out + ((size_t)c * N_ + n) * D_ + d4 * 4) = o;
    }
}

// ==================== launch ====================
extern "C" void kernel_launch(void* const* d_in, const int* in_sizes, int n_in,
                              void* d_out, int out_size) {
    const float* x    = (const float*)d_in[0];
    const int*   tgt  = (const int*)d_in[1];
    const float* prot = (const float*)d_in[2];
    const float* adj  = (const float*)d_in[3];
    const float* W1   = (const float*)d_in[4];
    const float* W2   = (const float*)d_in[5];
    const float* Wg   = (const float*)d_in[6];
    const float* bg   = (const float*)d_in[7];
    const float* Wc   = (const float*)d_in[8];
    const float* bc   = (const float*)d_in[9];

    float* pred_out  = (float*)d_out;
    float* proto_out = (float*)d_out + (size_t)B_ * C_;

    __nv_bfloat16 *ax_hi, *ax_lo, *ah_hi, *ah_lo, *nd_hi, *nd_lo, *gg_hi, *gg_lo;
    float* part;
    cudaGetSymbolAddress((void**)&ax_hi, g_ax_hi);   cudaGetSymbolAddress((void**)&ax_lo, g_ax_lo);
    cudaGetSymbolAddress((void**)&ah_hi, g_ah_hi);   cudaGetSymbolAddress((void**)&ah_lo, g_ah_lo);
    cudaGetSymbolAddress((void**)&nd_hi, g_nd_hi);   cudaGetSymbolAddress((void**)&nd_lo, g_nd_lo);
    cudaGetSymbolAddress((void**)&gg_hi, g_g_hi);    cudaGetSymbolAddress((void**)&gg_lo, g_g_lo);
    cudaGetSymbolAddress((void**)&part, g_part);

    cudaFuncSetAttribute(gemm_direct<0>, cudaFuncAttributeMaxDynamicSharedMemorySize, SMEM_TOTAL_GEMM);
    cudaFuncSetAttribute(gemm_direct<1>, cudaFuncAttributeMaxDynamicSharedMemorySize, SMEM_TOTAL_GEMM);

    // ax = adj @ x (+ hi/lo convert)
    adjmix_convert_kernel<<<(B_ * D_ + 255) / 256, 256>>>(x, adj, ax_hi, ax_lo, D_);

    // GEMM1: [1280,2048]@W1[2048,1024], S=2 (grid 8x10x2=160), 32 chunks/split
    gemm_direct<0><<<dim3(H_ / 128, (B_ * N_) / 128, 2), 256, SMEM_TOTAL_GEMM>>>(
        ax_hi, ax_lo, W1, part, nullptr, nullptr, B_ * N_, H_, H_, D_, 32);
    reduce_relu_adjmix_convert_kernel<<<(B_ * H_ + 255) / 256, 256>>>(part, 2, adj, ah_hi, ah_lo, H_);

    // GEMM2: [1280,1024]@W2[1024,2048], S=1 (grid 16x10=160), 32 chunks -> hi/lo direct
    gemm_direct<1><<<dim3(D_ / 128, (B_ * N_) / 128, 1), 256, SMEM_TOTAL_GEMM>>>(
        ah_hi, ah_lo, W2, nullptr, nd_hi, nd_lo, B_ * N_, D_, D_, H_, 32);

    // fc_g: [256,10240]@Wg[10240,2048], S=8 (grid 16x2x8=256), 40 chunks/split
    gemm_direct<0><<<dim3(D_ / 128, B_ / 128, 8), 256, SMEM_TOTAL_GEMM>>>(
        nd_hi, nd_lo, Wg, part, nullptr, nullptr, B_, D_, D_, N_ * D_, 40);
    reduce_bias_convert_kernel<<<(B_ * D_ + 255) / 256, 256>>>(part, 8, B_, D_, bg, gg_hi, gg_lo);

    // fc_cls: [256,2048]@Wc[2048,1000->pad 1024], S=8 (grid 8x2x8=128), 8 chunks/split
    gemm_direct<0><<<dim3(NPAD_C / 128, B_ / 128, 8), 256, SMEM_TOTAL_GEMM>>>(
        gg_hi, gg_lo, Wc, part, nullptr, nullptr, B_, NPAD_C, C_, D_, 8);
    reduce_bias_out_kernel<<<(B_ * C_ + 255) / 256, 256>>>(part, 8, NPAD_C, bc, pred_out);

    // prototypes
    class_meta_kernel<<<1, 1024>>>(tgt);
    proto_update_kernel<<<(C_ * (D_ / 4) + 255) / 256, 256>>>(x, prot, proto_out);
}

// round 6
// speedup vs baseline: 4.1902x; 1.0449x over previous
#include <cuda_runtime.h>
#include <cuda_bf16.h>
#include <cstdint>

#define B_ 256
#define N_ 5
#define D_ 2048
#define C_ 1000
#define H_ 1024
#define NPAD_C 1024
#define PROTO_M 0.999f
#define EPS_ 1e-12f

// ==================== scratch (static device globals) ====================
__device__ __nv_bfloat16 g_ax_hi[B_ * N_ * D_], g_ax_lo[B_ * N_ * D_];
__device__ __nv_bfloat16 g_ah_hi[B_ * N_ * H_], g_ah_lo[B_ * N_ * H_];
__device__ __nv_bfloat16 g_nd_hi[B_ * N_ * D_], g_nd_lo[B_ * N_ * D_];
__device__ __nv_bfloat16 g_g_hi[B_ * D_], g_g_lo[B_ * D_];
__device__ float g_part[16 * B_ * D_];   // split-K partials (8.4M floats)

__device__ float g_scale[C_];
__device__ int   g_off[C_ + 1];
__device__ int   g_idx[B_];
__device__ float g_w[B_];

// ==================== helpers ====================
__device__ __forceinline__ void split_bf16(float v, __nv_bfloat16& hi, __nv_bfloat16& lo) {
    hi = __float2bfloat16_rn(v);
    lo = __float2bfloat16_rn(v - __bfloat162float(hi));
}
__device__ __forceinline__ uint32_t smem_u32(const void* p) {
    uint32_t a;
    asm("{ .reg .u64 t; cvta.to.shared.u64 t, %1; cvt.u32.u64 %0, t; }" : "=r"(a) : "l"(p));
    return a;
}
__device__ __forceinline__ void cp_async16(uint32_t dst, const void* src) {
    asm volatile("cp.async.cg.shared.global [%0], [%1], 16;" :: "r"(dst), "l"(src));
}
__device__ __forceinline__ void cp_async16_z(uint32_t dst, const void* src, int sz) {
    asm volatile("cp.async.cg.shared.global [%0], [%1], 16, %2;" :: "r"(dst), "l"(src), "r"(sz));
}
__device__ __forceinline__ void cp_commit() { asm volatile("cp.async.commit_group;" ::: "memory"); }
__device__ __forceinline__ void cp_wait0() { asm volatile("cp.async.wait_group 0;" ::: "memory"); }

__device__ __forceinline__ void ldsm_x4(uint32_t* r, uint32_t addr) {
    asm volatile("ldmatrix.sync.aligned.m8n8.x4.shared.b16 {%0,%1,%2,%3}, [%4];"
        : "=r"(r[0]), "=r"(r[1]), "=r"(r[2]), "=r"(r[3]) : "r"(addr));
}
__device__ __forceinline__ void ldsm_x4_t(uint32_t* r, uint32_t addr) {
    asm volatile("ldmatrix.sync.aligned.m8n8.x4.trans.shared.b16 {%0,%1,%2,%3}, [%4];"
        : "=r"(r[0]), "=r"(r[1]), "=r"(r[2]), "=r"(r[3]) : "r"(addr));
}
__device__ __forceinline__ void mma16816(float* c, const uint32_t* a, uint32_t b0, uint32_t b1) {
    asm volatile(
        "mma.sync.aligned.m16n8k16.row.col.f32.bf16.bf16.f32 "
        "{%0,%1,%2,%3}, {%4,%5,%6,%7}, {%8,%9}, {%0,%1,%2,%3};"
        : "+f"(c[0]), "+f"(c[1]), "+f"(c[2]), "+f"(c[3])
        : "r"(a[0]), "r"(a[1]), "r"(a[2]), "r"(a[3]), "r"(b0), "r"(b1));
}

// ==================== adj-mix + hi/lo convert ====================
__global__ void adjmix_convert_kernel(const float* __restrict__ in,
                                      const float* __restrict__ adj,
                                      __nv_bfloat16* __restrict__ hi,
                                      __nv_bfloat16* __restrict__ lo, int F) {
    int t = blockIdx.x * blockDim.x + threadIdx.x;
    if (t >= B_ * F) return;
    int b = t / F, f = t % F;
    float xv[N_];
#pragma unroll
    for (int m = 0; m < N_; m++) xv[m] = in[((size_t)b * N_ + m) * F + f];
#pragma unroll
    for (int n = 0; n < N_; n++) {
        float s = 0.f;
#pragma unroll
        for (int m = 0; m < N_; m++) s += adj[n * N_ + m] * xv[m];
        __nv_bfloat16 h, l;
        split_bf16(s, h, l);
        hi[((size_t)b * N_ + n) * F + f] = h;
        lo[((size_t)b * N_ + n) * F + f] = l;
    }
}

// ==================== HMMA GEMM, direct f32-weight consumption ====================
#define SMEM_TOTAL_GEMM 108544
template <int WM>  // 0: f32 partial to P; 1: hi/lo bf16 direct to Ohi/Olo
__global__ void __launch_bounds__(256, 2)
gemm_direct(const __nv_bfloat16* __restrict__ A_hi, const __nv_bfloat16* __restrict__ A_lo,
            const float* __restrict__ W, float* __restrict__ P,
            __nv_bfloat16* __restrict__ Ohi, __nv_bfloat16* __restrict__ Olo,
            int M, int Npad, int Nw, int K, int NCper) {
    extern __shared__ __align__(16) uint8_t smem[];
    const uint32_t base = smem_u32(smem);
    const uint32_t oAhi = 0, oAlo = 20480, oW = 40960, oBhi = 73728, oBlo = 91136;
    const uint32_t strA = 10240, strW = 16384, strB = 8704;

    const int tid = threadIdx.x;
    const int lane = tid & 31, warp = tid >> 5;
    const int wr = warp & 3, wc = warp >> 2;     // 4x2 warp grid, warp tile 32x64
    const int row0 = blockIdx.y * 128, col0 = blockIdx.x * 128;
    const int c0 = blockIdx.z * NCper;

    const int ar0 = tid >> 2, aq0 = tid & 3;
    const int ar1 = (tid + 256) >> 2, aq1 = (tid + 256) & 3;
    int wk[4], wq[4], wsz[4];
#pragma unroll
    for (int i = 0; i < 4; i++) {
        int idx = tid + i * 256;
        wk[i] = idx >> 5; wq[i] = idx & 31;
        int v = (Nw - (col0 + wq[i] * 4)) * 4;
        wsz[i] = v < 0 ? 0 : (v > 16 ? 16 : v);
    }

    const int selRow = (lane & 7) + ((lane >> 3) & 1) * 8;
    const int selHi = (lane >> 4) & 1;
    const uint32_t aOff = (uint32_t)((wr * 32 + selRow) * 80 + selHi * 16);
    const uint32_t bOff = (uint32_t)(selRow * 272 + wc * 128 + selHi * 16);

    float acc[2][8][4] = {};

    auto stage = [&](int c, int buf) {
        int kk = c * 32;
        uint32_t da = base + oAhi + buf * strA;
        uint32_t dl = base + oAlo + buf * strA;
        uint32_t dw = base + oW + buf * strW;
        cp_async16(da + ar0 * 80 + aq0 * 16, A_hi + (size_t)(row0 + ar0) * K + kk + aq0 * 8);
        cp_async16(da + ar1 * 80 + aq1 * 16, A_hi + (size_t)(row0 + ar1) * K + kk + aq1 * 8);
        cp_async16(dl + ar0 * 80 + aq0 * 16, A_lo + (size_t)(row0 + ar0) * K + kk + aq0 * 8);
        cp_async16(dl + ar1 * 80 + aq1 * 16, A_lo + (size_t)(row0 + ar1) * K + kk + aq1 * 8);
#pragma unroll
        for (int i = 0; i < 4; i++) {
            const float* src = wsz[i] ? (W + (size_t)(kk + wk[i]) * Nw + col0 + wq[i] * 4) : W;
            cp_async16_z(dw + wk[i] * 512 + wq[i] * 16, src, wsz[i]);
        }
    };

    stage(c0, 0);
    cp_commit();

    for (int li = 0; li < NCper; li++) {
        const int buf = li & 1;
        cp_wait0();
        __syncthreads();
        if (li + 1 < NCper) { stage(c0 + li + 1, buf ^ 1); cp_commit(); }

        // convert W f32 tile -> bf16 hi/lo
        {
            const float4* wp = reinterpret_cast<const float4*>(smem + oW + buf * strW + tid * 64);
            uint32_t hw[8], lw[8];
#pragma unroll
            for (int i = 0; i < 4; i++) {
                float4 v = wp[i];
                __nv_bfloat16 h0, l0, h1, l1;
                split_bf16(v.x, h0, l0); split_bf16(v.y, h1, l1);
                __nv_bfloat162 hh; hh.x = h0; hh.y = h1;
                __nv_bfloat162 ll; ll.x = l0; ll.y = l1;
                hw[2 * i] = *reinterpret_cast<uint32_t*>(&hh);
                lw[2 * i] = *reinterpret_cast<uint32_t*>(&ll);
                split_bf16(v.z, h0, l0); split_bf16(v.w, h1, l1);
                hh.x = h0; hh.y = h1; ll.x = l0; ll.y = l1;
                hw[2 * i + 1] = *reinterpret_cast<uint32_t*>(&hh);
                lw[2 * i + 1] = *reinterpret_cast<uint32_t*>(&ll);
            }
            uint32_t wb = (uint32_t)((tid >> 3) * 272 + (tid & 7) * 32);
            uint4* oh = reinterpret_cast<uint4*>(smem + oBhi + buf * strB + wb);
            uint4* ol = reinterpret_cast<uint4*>(smem + oBlo + buf * strB + wb);
            oh[0] = make_uint4(hw[0], hw[1], hw[2], hw[3]);
            oh[1] = make_uint4(hw[4], hw[5], hw[6], hw[7]);
            ol[0] = make_uint4(lw[0], lw[1], lw[2], lw[3]);
            ol[1] = make_uint4(lw[4], lw[5], lw[6], lw[7]);
        }
        __syncthreads();

        const uint32_t ah = base + oAhi + buf * strA, al = base + oAlo + buf * strA;
        const uint32_t bh = base + oBhi + buf * strB, bl = base + oBlo + buf * strB;
#pragma unroll
        for (int ks = 0; ks < 2; ks++) {
            uint32_t fa[2][4], fb1[4][4], fb2[4][4];
            // pass 1: hiA * hiW
            ldsm_x4(fa[0], ah + aOff + ks * 32);
            ldsm_x4(fa[1], ah + aOff + 1280 + ks * 32);
#pragma unroll
            for (int p = 0; p < 4; p++) ldsm_x4_t(fb1[p], bh + bOff + ks * 4352 + p * 32);
#pragma unroll
            for (int mi = 0; mi < 2; mi++)
#pragma unroll
                for (int p = 0; p < 4; p++) {
                    mma16816(acc[mi][2 * p], fa[mi], fb1[p][0], fb1[p][1]);
                    mma16816(acc[mi][2 * p + 1], fa[mi], fb1[p][2], fb1[p][3]);
                }
            // pass 2: hiA * loW
#pragma unroll
            for (int p = 0; p < 4; p++) ldsm_x4_t(fb2[p], bl + bOff + ks * 4352 + p * 32);
#pragma unroll
            for (int mi = 0; mi < 2; mi++)
#pragma unroll
                for (int p = 0; p < 4; p++) {
                    mma16816(acc[mi][2 * p], fa[mi], fb2[p][0], fb2[p][1]);
                    mma16816(acc[mi][2 * p + 1], fa[mi], fb2[p][2], fb2[p][3]);
                }
            // pass 3: loA * hiW
            ldsm_x4(fa[0], al + aOff + ks * 32);
            ldsm_x4(fa[1], al + aOff + 1280 + ks * 32);
#pragma unroll
            for (int mi = 0; mi < 2; mi++)
#pragma unroll
                for (int p = 0; p < 4; p++) {
                    mma16816(acc[mi][2 * p], fa[mi], fb1[p][0], fb1[p][1]);
                    mma16816(acc[mi][2 * p + 1], fa[mi], fb1[p][2], fb1[p][3]);
                }
        }
    }

    // epilogue
    const int g = lane >> 2, tg = lane & 3;
    if (WM == 0) {
        size_t zb = (size_t)blockIdx.z * M * Npad;
#pragma unroll
        for (int mi = 0; mi < 2; mi++)
#pragma unroll
            for (int half = 0; half < 2; half++) {
                int r = row0 + wr * 32 + mi * 16 + g + half * 8;
                float* rowp = P + zb + (size_t)r * Npad + col0 + wc * 64;
#pragma unroll
                for (int ni = 0; ni < 8; ni++)
                    *reinterpret_cast<float2*>(rowp + ni * 8 + tg * 2) =
                        make_float2(acc[mi][ni][half * 2], acc[mi][ni][half * 2 + 1]);
            }
    } else {
#pragma unroll
        for (int mi = 0; mi < 2; mi++)
#pragma unroll
            for (int half = 0; half < 2; half++) {
                int r = row0 + wr * 32 + mi * 16 + g + half * 8;
                size_t rb = (size_t)r * Npad + col0 + wc * 64;
#pragma unroll
                for (int ni = 0; ni < 8; ni++) {
                    __nv_bfloat16 h0, l0, h1, l1;
                    split_bf16(acc[mi][ni][half * 2], h0, l0);
                    split_bf16(acc[mi][ni][half * 2 + 1], h1, l1);
                    __nv_bfloat162 hh; hh.x = h0; hh.y = h1;
                    __nv_bfloat162 ll; ll.x = l0; ll.y = l1;
                    *reinterpret_cast<__nv_bfloat162*>(Ohi + rb + ni * 8 + tg * 2) = hh;
                    *reinterpret_cast<__nv_bfloat162*>(Olo + rb + ni * 8 + tg * 2) = ll;
                }
            }
    }
}

// ==================== reduce epilogues ====================
__global__ void reduce_relu_adjmix_convert_kernel(const float* __restrict__ P, int S,
                                                  const float* __restrict__ adj,
                                                  __nv_bfloat16* __restrict__ hi,
                                                  __nv_bfloat16* __restrict__ lo, int F) {
    int t = blockIdx.x * blockDim.x + threadIdx.x;
    if (t >= B_ * F) return;
    int b = t / F, f = t % F;
    float hv[N_];
#pragma unroll
    for (int m = 0; m < N_; m++) {
        float s = 0.f;
        for (int j = 0; j < S; j++)
            s += P[(size_t)j * (B_ * N_ * F) + ((size_t)b * N_ + m) * F + f];
        hv[m] = fmaxf(s, 0.f);
    }
#pragma unroll
    for (int n = 0; n < N_; n++) {
        float s = 0.f;
#pragma unroll
        for (int m = 0; m < N_; m++) s += adj[n * N_ + m] * hv[m];
        __nv_bfloat16 h, l;
        split_bf16(s, h, l);
        hi[((size_t)b * N_ + n) * F + f] = h;
        lo[((size_t)b * N_ + n) * F + f] = l;
    }
}

__global__ void reduce_convert_kernel(const float* __restrict__ P, int S, size_t len,
                                      __nv_bfloat16* __restrict__ hi,
                                      __nv_bfloat16* __restrict__ lo) {
    size_t t = (size_t)blockIdx.x * blockDim.x + threadIdx.x;
    if (t >= len) return;
    float s = 0.f;
    for (int j = 0; j < S; j++) s += P[(size_t)j * len + t];
    __nv_bfloat16 h, l;
    split_bf16(s, h, l);
    hi[t] = h;
    lo[t] = l;
}

__global__ void reduce_bias_convert_kernel(const float* __restrict__ P, int S, int M, int N,
                                           const float* __restrict__ bias,
                                           __nv_bfloat16* __restrict__ hi,
                                           __nv_bfloat16* __restrict__ lo) {
    int t = blockIdx.x * blockDim.x + threadIdx.x;
    if (t >= M * N) return;
    float s = bias[t % N];
    for (int j = 0; j < S; j++) s += P[(size_t)j * M * N + t];
    __nv_bfloat16 h, l;
    split_bf16(s, h, l);
    hi[t] = h;
    lo[t] = l;
}

__global__ void reduce_bias_out_kernel(const float* __restrict__ P, int S, int Npad,
                                       const float* __restrict__ bias,
                                       float* __restrict__ out) {
    int t = blockIdx.x * blockDim.x + threadIdx.x;
    if (t >= B_ * C_) return;
    int b = t / C_, n = t % C_;
    float s = bias[n];
    for (int j = 0; j < S; j++) s += P[(size_t)j * B_ * Npad + (size_t)b * Npad + n];
    out[t] = s;
}

// ==================== prototype EMA (closed form), parallel metadata ====================
__global__ void class_meta_kernel(const int* __restrict__ target) {  // 1 block, 1024 thr
    __shared__ int cnt[1024];
    __shared__ int scan[1024];
    __shared__ int t_s[B_];
    __shared__ int rank_s[B_];
    int tid = threadIdx.x;
    cnt[tid] = 0;
    __syncthreads();
    if (tid < B_) t_s[tid] = target[tid];
    __syncthreads();
    if (tid < B_) {
        int c = t_s[tid], r = 0;
        for (int j = 0; j < tid; j++) r += (t_s[j] == c) ? 1 : 0;
        rank_s[tid] = r;
        atomicAdd(&cnt[c], 1);
    }
    __syncthreads();
    if (tid < C_) g_scale[tid] = powf(PROTO_M, (float)cnt[tid]);
    scan[tid] = cnt[tid];
    __syncthreads();
    for (int ofs = 1; ofs < 1024; ofs <<= 1) {
        int v = (tid >= ofs) ? scan[tid - ofs] : 0;
        __syncthreads();
        scan[tid] += v;
        __syncthreads();
    }
    if (tid < C_) g_off[tid] = scan[tid] - cnt[tid];
    if (tid == 0) g_off[C_] = B_;
    __syncthreads();
    if (tid < B_) {
        int c = t_s[tid];
        int p = (scan[c] - cnt[c]) + rank_s[tid];
        g_idx[p] = tid;
        g_w[p] = (1.0f - PROTO_M) * powf(PROTO_M, (float)(cnt[c] - 1 - rank_s[tid]));
    }
}

__global__ void proto_update_kernel(const float* __restrict__ x,
                                    const float* __restrict__ protos,
                                    float* __restrict__ out) {
    int t = blockIdx.x * blockDim.x + threadIdx.x;
    const int D4 = D_ / 4;
    if (t >= C_ * D4) return;
    int c = t / D4, d4 = t % D4;
    float s = g_scale[c];
    float4 v[N_];
#pragma unroll
    for (int n = 0; n < N_; n++) {
        float4 p = *reinterpret_cast<const float4*>(protos + ((size_t)c * N_ + n) * D_ + d4 * 4);
        v[n] = make_float4(p.x * s, p.y * s, p.z * s, p.w * s);
    }
    int e = g_off[c + 1];
    for (int j = g_off[c]; j < e; j++) {
        int i = g_idx[j];
        float w = g_w[j];
#pragma unroll
        for (int n = 0; n < N_; n++) {
            float4 xv = *reinterpret_cast<const float4*>(x + ((size_t)i * N_ + n) * D_ + d4 * 4);
            v[n].x += w * xv.x; v[n].y += w * xv.y;
            v[n].z += w * xv.z; v[n].w += w * xv.w;
        }
    }
    float4 nrm4 = make_float4(0.f, 0.f, 0.f, 0.f);
#pragma unroll
    for (int n = 0; n < N_; n++) {
        nrm4.x += v[n].x * v[n].x; nrm4.y += v[n].y * v[n].y;
        nrm4.z += v[n].z * v[n].z; nrm4.w += v[n].w * v[n].w;
    }
    float4 inv = make_float4(1.f / fmaxf(sqrtf(nrm4.x), EPS_), 1.f / fmaxf(sqrtf(nrm4.y), EPS_),
                             1.f / fmaxf(sqrtf(nrm4.z), EPS_), 1.f / fmaxf(sqrtf(nrm4.w), EPS_));
#pragma unroll
    for (int n = 0; n < N_; n++) {
        float4 o = make_float4(v[n].x * inv.x, v[n].y * inv.y, v[n].z * inv.z, v[n].w * inv.w);
        *reinterpret_cast<float4*>(out + ((size_t)c * N_ + n) * D_ + d4 * 4) = o;
    }
}

// ==================== launch ====================
extern "C" void kernel_launch(void* const* d_in, const int* in_sizes, int n_in,
                              void* d_out, int out_size) {
    const float* x    = (const float*)d_in[0];
    const int*   tgt  = (const int*)d_in[1];
    const float* prot = (const float*)d_in[2];
    const float* adj  = (const float*)d_in[3];
    const float* W1   = (const float*)d_in[4];
    const float* W2   = (const float*)d_in[5];
    const float* Wg   = (const float*)d_in[6];
    const float* bg   = (const float*)d_in[7];
    const float* Wc   = (const float*)d_in[8];
    const float* bc   = (const float*)d_in[9];

    float* pred_out  = (float*)d_out;
    float* proto_out = (float*)d_out + (size_t)B_ * C_;

    __nv_bfloat16 *ax_hi, *ax_lo, *ah_hi, *ah_lo, *nd_hi, *nd_lo, *gg_hi, *gg_lo;
    float* part;
    cudaGetSymbolAddress((void**)&ax_hi, g_ax_hi);   cudaGetSymbolAddress((void**)&ax_lo, g_ax_lo);
    cudaGetSymbolAddress((void**)&ah_hi, g_ah_hi);   cudaGetSymbolAddress((void**)&ah_lo, g_ah_lo);
    cudaGetSymbolAddress((void**)&nd_hi, g_nd_hi);   cudaGetSymbolAddress((void**)&nd_lo, g_nd_lo);
    cudaGetSymbolAddress((void**)&gg_hi, g_g_hi);    cudaGetSymbolAddress((void**)&gg_lo, g_g_lo);
    cudaGetSymbolAddress((void**)&part, g_part);

    cudaFuncSetAttribute(gemm_direct<0>, cudaFuncAttributeMaxDynamicSharedMemorySize, SMEM_TOTAL_GEMM);
    cudaFuncSetAttribute(gemm_direct<1>, cudaFuncAttributeMaxDynamicSharedMemorySize, SMEM_TOTAL_GEMM);

    // ax = adj @ x (+ hi/lo convert)
    adjmix_convert_kernel<<<(B_ * D_ + 255) / 256, 256>>>(x, adj, ax_hi, ax_lo, D_);

    // GEMM1: [1280,2048]@W1[2048,1024], S=4 (grid 8x10x4=320), 16 chunks/split
    gemm_direct<0><<<dim3(H_ / 128, (B_ * N_) / 128, 4), 256, SMEM_TOTAL_GEMM>>>(
        ax_hi, ax_lo, W1, part, nullptr, nullptr, B_ * N_, H_, H_, D_, 16);
    reduce_relu_adjmix_convert_kernel<<<(B_ * H_ + 255) / 256, 256>>>(part, 4, adj, ah_hi, ah_lo, H_);

    // GEMM2: [1280,1024]@W2[1024,2048], S=2 (grid 16x10x2=320), 16 chunks/split -> f32 part
    gemm_direct<0><<<dim3(D_ / 128, (B_ * N_) / 128, 2), 256, SMEM_TOTAL_GEMM>>>(
        ah_hi, ah_lo, W2, part, nullptr, nullptr, B_ * N_, D_, D_, H_, 16);
    reduce_convert_kernel<<<((int)((size_t)B_ * N_ * D_) + 255) / 256, 256>>>(
        part, 2, (size_t)B_ * N_ * D_, nd_hi, nd_lo);

    // fc_g: [256,10240]@Wg[10240,2048], S=10 (grid 16x2x10=320), 32 chunks/split
    gemm_direct<0><<<dim3(D_ / 128, B_ / 128, 10), 256, SMEM_TOTAL_GEMM>>>(
        nd_hi, nd_lo, Wg, part, nullptr, nullptr, B_, D_, D_, N_ * D_, 32);
    reduce_bias_convert_kernel<<<(B_ * D_ + 255) / 256, 256>>>(part, 10, B_, D_, bg, gg_hi, gg_lo);

    // fc_cls: [256,2048]@Wc[2048,1000->pad 1024], S=16 (grid 8x2x16=256), 4 chunks/split
    gemm_direct<0><<<dim3(NPAD_C / 128, B_ / 128, 16), 256, SMEM_TOTAL_GEMM>>>(
        gg_hi, gg_lo, Wc, part, nullptr, nullptr, B_, NPAD_C, C_, D_, 4);
    reduce_bias_out_kernel<<<(B_ * C_ + 255) / 256, 256>>>(part, 16, NPAD_C, bc, pred_out);

    // prototypes
    class_meta_kernel<<<1, 1024>>>(tgt);
    proto_update_kernel<<<(C_ * (D_ / 4) + 255) / 256, 256>>>(x, prot, proto_out);
}

// round 8
// speedup vs baseline: 4.8320x; 1.1532x over previous
#include <cuda_runtime.h>
#include <cuda_bf16.h>
#include <cstdint>

#define B_ 256
#define N_ 5
#define D_ 2048
#define C_ 1000
#define H_ 1024
#define NPAD_C 1024
#define PROTO_M 0.999f
#define EPS_ 1e-12f

// ==================== scratch (static device globals) ====================
__device__ __nv_bfloat16 g_ax_hi[B_ * N_ * D_], g_ax_lo[B_ * N_ * D_];
__device__ __nv_bfloat16 g_ah_hi[B_ * N_ * H_], g_ah_lo[B_ * N_ * H_];
__device__ __nv_bfloat16 g_nd_hi[B_ * N_ * D_], g_nd_lo[B_ * N_ * D_];
__device__ __nv_bfloat16 g_g_hi[B_ * D_], g_g_lo[B_ * D_];
__device__ float g_part[16 * B_ * D_];   // split-K partials

__device__ float g_scale[C_];
__device__ int   g_off[C_ + 1];
__device__ int   g_idx[B_];
__device__ float g_w[B_];

// ==================== helpers ====================
__device__ __forceinline__ void split_bf16(float v, __nv_bfloat16& hi, __nv_bfloat16& lo) {
    hi = __float2bfloat16_rn(v);
    lo = __float2bfloat16_rn(v - __bfloat162float(hi));
}
__device__ __forceinline__ uint32_t smem_u32(const void* p) {
    uint32_t a;
    asm("{ .reg .u64 t; cvta.to.shared.u64 t, %1; cvt.u32.u64 %0, t; }" : "=r"(a) : "l"(p));
    return a;
}
__device__ __forceinline__ void cp_async16(uint32_t dst, const void* src) {
    asm volatile("cp.async.cg.shared.global [%0], [%1], 16;" :: "r"(dst), "l"(src));
}
__device__ __forceinline__ void cp_async16_z(uint32_t dst, const void* src, int sz) {
    asm volatile("cp.async.cg.shared.global [%0], [%1], 16, %2;" :: "r"(dst), "l"(src), "r"(sz));
}
__device__ __forceinline__ void cp_commit() { asm volatile("cp.async.commit_group;" ::: "memory"); }
__device__ __forceinline__ void cp_wait0() { asm volatile("cp.async.wait_group 0;" ::: "memory"); }

__device__ __forceinline__ void ldsm_x4(uint32_t* r, uint32_t addr) {
    asm volatile("ldmatrix.sync.aligned.m8n8.x4.shared.b16 {%0,%1,%2,%3}, [%4];"
        : "=r"(r[0]), "=r"(r[1]), "=r"(r[2]), "=r"(r[3]) : "r"(addr));
}
__device__ __forceinline__ void ldsm_x4_t(uint32_t* r, uint32_t addr) {
    asm volatile("ldmatrix.sync.aligned.m8n8.x4.trans.shared.b16 {%0,%1,%2,%3}, [%4];"
        : "=r"(r[0]), "=r"(r[1]), "=r"(r[2]), "=r"(r[3]) : "r"(addr));
}
__device__ __forceinline__ void mma16816(float* c, const uint32_t* a, uint32_t b0, uint32_t b1) {
    asm volatile(
        "mma.sync.aligned.m16n8k16.row.col.f32.bf16.bf16.f32 "
        "{%0,%1,%2,%3}, {%4,%5,%6,%7}, {%8,%9}, {%0,%1,%2,%3};"
        : "+f"(c[0]), "+f"(c[1]), "+f"(c[2]), "+f"(c[3])
        : "r"(a[0]), "r"(a[1]), "r"(a[2]), "r"(a[3]), "r"(b0), "r"(b1));
}

// ==================== adj-mix + hi/lo convert ====================
__global__ void adjmix_convert_kernel(const float* __restrict__ in,
                                      const float* __restrict__ adj,
                                      __nv_bfloat16* __restrict__ hi,
                                      __nv_bfloat16* __restrict__ lo, int F) {
    int t = blockIdx.x * blockDim.x + threadIdx.x;
    if (t >= B_ * F) return;
    int b = t / F, f = t % F;
    float xv[N_];
#pragma unroll
    for (int m = 0; m < N_; m++) xv[m] = in[((size_t)b * N_ + m) * F + f];
#pragma unroll
    for (int n = 0; n < N_; n++) {
        float s = 0.f;
#pragma unroll
        for (int m = 0; m < N_; m++) s += adj[n * N_ + m] * xv[m];
        __nv_bfloat16 h, l;
        split_bf16(s, h, l);
        hi[((size_t)b * N_ + n) * F + f] = h;
        lo[((size_t)b * N_ + n) * F + f] = l;
    }
}

// ==================== HMMA GEMM, pipelined convert (self-data, race-free) ====================
// Smem: Ahi@0, Alo@20480 (80B rows), Wf32@40960 (512B rows), Bhi@73728,
// Blo@91136 (272B rows). All double-buffered. Total 108544 B.
#define SMEM_TOTAL_GEMM 108544
template <int WM>
__global__ void __launch_bounds__(256, 2)
gemm_direct(const __nv_bfloat16* __restrict__ A_hi, const __nv_bfloat16* __restrict__ A_lo,
            const float* __restrict__ W, float* __restrict__ P,
            __nv_bfloat16* __restrict__ Ohi, __nv_bfloat16* __restrict__ Olo,
            int M, int Npad, int Nw, int K, int NCper) {
    extern __shared__ __align__(16) uint8_t smem[];
    const uint32_t base = smem_u32(smem);
    const uint32_t oAhi = 0, oAlo = 20480, oW = 40960, oBhi = 73728, oBlo = 91136;
    const uint32_t strA = 10240, strW = 16384, strB = 8704;

    const int tid = threadIdx.x;
    const int lane = tid & 31, warp = tid >> 5;
    const int wr = warp & 3, wc = warp >> 2;     // 4x2 warp grid, warp tile 32x64
    const int row0 = blockIdx.y * 128, col0 = blockIdx.x * 128;
    const int c0 = blockIdx.z * NCper;

    const int ar0 = tid >> 2, aq0 = tid & 3;
    const int ar1 = (tid + 256) >> 2, aq1 = (tid + 256) & 3;
    int wk[4], wq[4], wsz[4];
#pragma unroll
    for (int i = 0; i < 4; i++) {
        int idx = tid + i * 256;
        wk[i] = idx >> 5; wq[i] = idx & 31;
        int v = (Nw - (col0 + wq[i] * 4)) * 4;
        wsz[i] = v < 0 ? 0 : (v > 16 ? 16 : v);
    }

    const int selRow = (lane & 7) + ((lane >> 3) & 1) * 8;
    const int selHi = (lane >> 4) & 1;
    const uint32_t aOff = (uint32_t)((wr * 32 + selRow) * 80 + selHi * 16);
    const uint32_t bOff = (uint32_t)(selRow * 272 + wc * 128 + selHi * 16);

    float acc[2][8][4] = {};

    auto stage = [&](int c, int buf) {
        int kk = c * 32;
        uint32_t da = base + oAhi + buf * strA;
        uint32_t dl = base + oAlo + buf * strA;
        uint32_t dw = base + oW + buf * strW;
        cp_async16(da + ar0 * 80 + aq0 * 16, A_hi + (size_t)(row0 + ar0) * K + kk + aq0 * 8);
        cp_async16(da + ar1 * 80 + aq1 * 16, A_hi + (size_t)(row0 + ar1) * K + kk + aq1 * 8);
        cp_async16(dl + ar0 * 80 + aq0 * 16, A_lo + (size_t)(row0 + ar0) * K + kk + aq0 * 8);
        cp_async16(dl + ar1 * 80 + aq1 * 16, A_lo + (size_t)(row0 + ar1) * K + kk + aq1 * 8);
#pragma unroll
        for (int i = 0; i < 4; i++) {
            const float* src = wsz[i] ? (W + (size_t)(kk + wk[i]) * Nw + col0 + wq[i] * 4) : W;
            cp_async16_z(dw + wk[i] * 512 + wq[i] * 16, src, wsz[i]);
        }
    };

    // convert W f32 tile (buf) -> bf16 hi/lo (buf), SELF-DATA ONLY:
    // each thread converts exactly the 4 quads it staged via cp.async
    // (safe after cp_wait0 without a block barrier).
    auto convert = [&](int buf) {
        const uint32_t dw = base + oW + buf * strW;
        const uint32_t bh = base + oBhi + buf * strB;
        const uint32_t bl = base + oBlo + buf * strB;
#pragma unroll
        for (int i = 0; i < 4; i++) {
            int idx = tid + i * 256;
            float4 v = *reinterpret_cast<const float4*>(smem + (oW + buf * strW) + idx * 16);
            __nv_bfloat16 h0, l0, h1, l1, h2, l2, h3, l3;
            split_bf16(v.x, h0, l0); split_bf16(v.y, h1, l1);
            split_bf16(v.z, h2, l2); split_bf16(v.w, h3, l3);
            __nv_bfloat162 hA, hB, lA, lB;
            hA.x = h0; hA.y = h1; hB.x = h2; hB.y = h3;
            lA.x = l0; lA.y = l1; lB.x = l2; lB.y = l3;
            uint2 hp = make_uint2(*reinterpret_cast<uint32_t*>(&hA),
                                  *reinterpret_cast<uint32_t*>(&hB));
            uint2 lp = make_uint2(*reinterpret_cast<uint32_t*>(&lA),
                                  *reinterpret_cast<uint32_t*>(&lB));
            uint32_t off = (uint32_t)(wk[i] * 272 + wq[i] * 8);
            *reinterpret_cast<uint2*>(smem + (oBhi + buf * strB) + off) = hp;
            *reinterpret_cast<uint2*>(smem + (oBlo + buf * strB) + off) = lp;
        }
        (void)dw; (void)bh; (void)bl;
    };

    // prologue
    stage(c0, 0);
    cp_commit();
    cp_wait0();
    convert(0);
    __syncthreads();                      // publish bf16(0) to all warps
    if (NCper > 1) { stage(c0 + 1, 1); cp_commit(); }

    for (int li = 0; li < NCper; li++) {
        const int buf = li & 1;
        const uint32_t ah = base + oAhi + buf * strA, al = base + oAlo + buf * strA;
        const uint32_t bh = base + oBhi + buf * strB, bl = base + oBlo + buf * strB;

        // ---- MMA chunk li ----
#pragma unroll
        for (int ks = 0; ks < 2; ks++) {
            uint32_t fa[2][4], fb1[4][4], fb2[4][4];
            ldsm_x4(fa[0], ah + aOff + ks * 32);
            ldsm_x4(fa[1], ah + aOff + 1280 + ks * 32);
#pragma unroll
            for (int p = 0; p < 4; p++) ldsm_x4_t(fb1[p], bh + bOff + ks * 4352 + p * 32);
#pragma unroll
            for (int mi = 0; mi < 2; mi++)
#pragma unroll
                for (int p = 0; p < 4; p++) {
                    mma16816(acc[mi][2 * p], fa[mi], fb1[p][0], fb1[p][1]);
                    mma16816(acc[mi][2 * p + 1], fa[mi], fb1[p][2], fb1[p][3]);
                }
#pragma unroll
            for (int p = 0; p < 4; p++) ldsm_x4_t(fb2[p], bl + bOff + ks * 4352 + p * 32);
#pragma unroll
            for (int mi = 0; mi < 2; mi++)
#pragma unroll
                for (int p = 0; p < 4; p++) {
                    mma16816(acc[mi][2 * p], fa[mi], fb2[p][0], fb2[p][1]);
                    mma16816(acc[mi][2 * p + 1], fa[mi], fb2[p][2], fb2[p][3]);
                }
            ldsm_x4(fa[0], al + aOff + ks * 32);
            ldsm_x4(fa[1], al + aOff + 1280 + ks * 32);
#pragma unroll
            for (int mi = 0; mi < 2; mi++)
#pragma unroll
                for (int p = 0; p < 4; p++) {
                    mma16816(acc[mi][2 * p], fa[mi], fb1[p][0], fb1[p][1]);
                    mma16816(acc[mi][2 * p + 1], fa[mi], fb1[p][2], fb1[p][3]);
                }
        }

        // ---- overlap: wait own cp(li+1), convert own quads (no barrier needed) ----
        if (li + 1 < NCper) {
            cp_wait0();
            convert(buf ^ 1);
        }
        __syncthreads();  // publish bf16(li+1); all warps done reading A/W buf li
        if (li + 2 < NCper) { stage(c0 + li + 2, buf); cp_commit(); }
    }

    // epilogue
    const int g = lane >> 2, tg = lane & 3;
    if (WM == 0) {
        size_t zb = (size_t)blockIdx.z * M * Npad;
#pragma unroll
        for (int mi = 0; mi < 2; mi++)
#pragma unroll
            for (int half = 0; half < 2; half++) {
                int r = row0 + wr * 32 + mi * 16 + g + half * 8;
                float* rowp = P + zb + (size_t)r * Npad + col0 + wc * 64;
#pragma unroll
                for (int ni = 0; ni < 8; ni++)
                    *reinterpret_cast<float2*>(rowp + ni * 8 + tg * 2) =
                        make_float2(acc[mi][ni][half * 2], acc[mi][ni][half * 2 + 1]);
            }
    } else {
#pragma unroll
        for (int mi = 0; mi < 2; mi++)
#pragma unroll
            for (int half = 0; half < 2; half++) {
                int r = row0 + wr * 32 + mi * 16 + g + half * 8;
                size_t rb = (size_t)r * Npad + col0 + wc * 64;
#pragma unroll
                for (int ni = 0; ni < 8; ni++) {
                    __nv_bfloat16 h0, l0, h1, l1;
                    split_bf16(acc[mi][ni][half * 2], h0, l0);
                    split_bf16(acc[mi][ni][half * 2 + 1], h1, l1);
                    __nv_bfloat162 hh; hh.x = h0; hh.y = h1;
                    __nv_bfloat162 ll; ll.x = l0; ll.y = l1;
                    *reinterpret_cast<__nv_bfloat162*>(Ohi + rb + ni * 8 + tg * 2) = hh;
                    *reinterpret_cast<__nv_bfloat162*>(Olo + rb + ni * 8 + tg * 2) = ll;
                }
            }
    }
}

// ==================== reduce epilogues ====================
__global__ void reduce_relu_adjmix_convert_kernel(const float* __restrict__ P, int S,
                                                  const float* __restrict__ adj,
                                                  __nv_bfloat16* __restrict__ hi,
                                                  __nv_bfloat16* __restrict__ lo, int F) {
    int t = blockIdx.x * blockDim.x + threadIdx.x;
    if (t >= B_ * F) return;
    int b = t / F, f = t % F;
    float hv[N_];
#pragma unroll
    for (int m = 0; m < N_; m++) {
        float s = 0.f;
        for (int j = 0; j < S; j++)
            s += P[(size_t)j * (B_ * N_ * F) + ((size_t)b * N_ + m) * F + f];
        hv[m] = fmaxf(s, 0.f);
    }
#pragma unroll
    for (int n = 0; n < N_; n++) {
        float s = 0.f;
#pragma unroll
        for (int m = 0; m < N_; m++) s += adj[n * N_ + m] * hv[m];
        __nv_bfloat16 h, l;
        split_bf16(s, h, l);
        hi[((size_t)b * N_ + n) * F + f] = h;
        lo[((size_t)b * N_ + n) * F + f] = l;
    }
}

__global__ void reduce_convert_kernel(const float* __restrict__ P, int S, size_t len,
                                      __nv_bfloat16* __restrict__ hi,
                                      __nv_bfloat16* __restrict__ lo) {
    size_t t = (size_t)blockIdx.x * blockDim.x + threadIdx.x;
    if (t >= len) return;
    float s = 0.f;
    for (int j = 0; j < S; j++) s += P[(size_t)j * len + t];
    __nv_bfloat16 h, l;
    split_bf16(s, h, l);
    hi[t] = h;
    lo[t] = l;
}

__global__ void reduce_bias_convert_kernel(const float* __restrict__ P, int S, int M, int N,
                                           const float* __restrict__ bias,
                                           __nv_bfloat16* __restrict__ hi,
                                           __nv_bfloat16* __restrict__ lo) {
    int t = blockIdx.x * blockDim.x + threadIdx.x;
    if (t >= M * N) return;
    float s = bias[t % N];
    for (int j = 0; j < S; j++) s += P[(size_t)j * M * N + t];
    __nv_bfloat16 h, l;
    split_bf16(s, h, l);
    hi[t] = h;
    lo[t] = l;
}

__global__ void reduce_bias_out_kernel(const float* __restrict__ P, int S, int Npad,
                                       const float* __restrict__ bias,
                                       float* __restrict__ out) {
    int t = blockIdx.x * blockDim.x + threadIdx.x;
    if (t >= B_ * C_) return;
    int b = t / C_, n = t % C_;
    float s = bias[n];
    for (int j = 0; j < S; j++) s += P[(size_t)j * B_ * Npad + (size_t)b * Npad + n];
    out[t] = s;
}

// ==================== prototype EMA (closed form), parallel metadata ====================
__global__ void class_meta_kernel(const int* __restrict__ target) {  // 1 block, 1024 thr
    __shared__ int cnt[1024];
    __shared__ int scan[1024];
    __shared__ int t_s[B_];
    __shared__ int rank_s[B_];
    int tid = threadIdx.x;
    cnt[tid] = 0;
    __syncthreads();
    if (tid < B_) t_s[tid] = target[tid];
    __syncthreads();
    if (tid < B_) {
        int c = t_s[tid], r = 0;
        for (int j = 0; j < tid; j++) r += (t_s[j] == c) ? 1 : 0;
        rank_s[tid] = r;
        atomicAdd(&cnt[c], 1);
    }
    __syncthreads();
    if (tid < C_) g_scale[tid] = powf(PROTO_M, (float)cnt[tid]);
    scan[tid] = cnt[tid];
    __syncthreads();
    for (int ofs = 1; ofs < 1024; ofs <<= 1) {
        int v = (tid >= ofs) ? scan[tid - ofs] : 0;
        __syncthreads();
        scan[tid] += v;
        __syncthreads();
    }
    if (tid < C_) g_off[tid] = scan[tid] - cnt[tid];
    if (tid == 0) g_off[C_] = B_;
    __syncthreads();
    if (tid < B_) {
        int c = t_s[tid];
        int p = (scan[c] - cnt[c]) + rank_s[tid];
        g_idx[p] = tid;
        g_w[p] = (1.0f - PROTO_M) * powf(PROTO_M, (float)(cnt[c] - 1 - rank_s[tid]));
    }
}

__global__ void proto_update_kernel(const float* __restrict__ x,
                                    const float* __restrict__ protos,
                                    float* __restrict__ out) {
    int t = blockIdx.x * blockDim.x + threadIdx.x;
    const int D4 = D_ / 4;
    if (t >= C_ * D4) return;
    int c = t / D4, d4 = t % D4;
    float s = g_scale[c];
    float4 v[N_];
#pragma unroll
    for (int n = 0; n < N_; n++) {
        float4 p = *reinterpret_cast<const float4*>(protos + ((size_t)c * N_ + n) * D_ + d4 * 4);
        v[n] = make_float4(p.x * s, p.y * s, p.z * s, p.w * s);
    }
    int e = g_off[c + 1];
    for (int j = g_off[c]; j < e; j++) {
        int i = g_idx[j];
        float w = g_w[j];
#pragma unroll
        for (int n = 0; n < N_; n++) {
            float4 xv = *reinterpret_cast<const float4*>(x + ((size_t)i * N_ + n) * D_ + d4 * 4);
            v[n].x += w * xv.x; v[n].y += w * xv.y;
            v[n].z += w * xv.z; v[n].w += w * xv.w;
        }
    }
    float4 nrm4 = make_float4(0.f, 0.f, 0.f, 0.f);
#pragma unroll
    for (int n = 0; n < N_; n++) {
        nrm4.x += v[n].x * v[n].x; nrm4.y += v[n].y * v[n].y;
        nrm4.z += v[n].z * v[n].z; nrm4.w += v[n].w * v[n].w;
    }
    float4 inv = make_float4(1.f / fmaxf(sqrtf(nrm4.x), EPS_), 1.f / fmaxf(sqrtf(nrm4.y), EPS_),
                             1.f / fmaxf(sqrtf(nrm4.z), EPS_), 1.f / fmaxf(sqrtf(nrm4.w), EPS_));
#pragma unroll
    for (int n = 0; n < N_; n++) {
        float4 o = make_float4(v[n].x * inv.x, v[n].y * inv.y, v[n].z * inv.z, v[n].w * inv.w);
        *reinterpret_cast<float4*>(out + ((size_t)c * N_ + n) * D_ + d4 * 4) = o;
    }
}

// ==================== launch ====================
extern "C" void kernel_launch(void* const* d_in, const int* in_sizes, int n_in,
                              void* d_out, int out_size) {
    const float* x    = (const float*)d_in[0];
    const int*   tgt  = (const int*)d_in[1];
    const float* prot = (const float*)d_in[2];
    const float* adj  = (const float*)d_in[3];
    const float* W1   = (const float*)d_in[4];
    const float* W2   = (const float*)d_in[5];
    const float* Wg   = (const float*)d_in[6];
    const float* bg   = (const float*)d_in[7];
    const float* Wc   = (const float*)d_in[8];
    const float* bc   = (const float*)d_in[9];

    float* pred_out  = (float*)d_out;
    float* proto_out = (float*)d_out + (size_t)B_ * C_;

    __nv_bfloat16 *ax_hi, *ax_lo, *ah_hi, *ah_lo, *nd_hi, *nd_lo, *gg_hi, *gg_lo;
    float* part;
    cudaGetSymbolAddress((void**)&ax_hi, g_ax_hi);   cudaGetSymbolAddress((void**)&ax_lo, g_ax_lo);
    cudaGetSymbolAddress((void**)&ah_hi, g_ah_hi);   cudaGetSymbolAddress((void**)&ah_lo, g_ah_lo);
    cudaGetSymbolAddress((void**)&nd_hi, g_nd_hi);   cudaGetSymbolAddress((void**)&nd_lo, g_nd_lo);
    cudaGetSymbolAddress((void**)&gg_hi, g_g_hi);    cudaGetSymbolAddress((void**)&gg_lo, g_g_lo);
    cudaGetSymbolAddress((void**)&part, g_part);

    cudaFuncSetAttribute(gemm_direct<0>, cudaFuncAttributeMaxDynamicSharedMemorySize, SMEM_TOTAL_GEMM);
    cudaFuncSetAttribute(gemm_direct<1>, cudaFuncAttributeMaxDynamicSharedMemorySize, SMEM_TOTAL_GEMM);

    // ax = adj @ x (+ hi/lo convert)
    adjmix_convert_kernel<<<(B_ * D_ + 255) / 256, 256>>>(x, adj, ax_hi, ax_lo, D_);

    // GEMM1: [1280,2048]@W1[2048,1024], S=4 (grid 320), 16 chunks/split
    gemm_direct<0><<<dim3(H_ / 128, (B_ * N_) / 128, 4), 256, SMEM_TOTAL_GEMM>>>(
        ax_hi, ax_lo, W1, part, nullptr, nullptr, B_ * N_, H_, H_, D_, 16);
    reduce_relu_adjmix_convert_kernel<<<(B_ * H_ + 255) / 256, 256>>>(part, 4, adj, ah_hi, ah_lo, H_);

    // GEMM2: [1280,1024]@W2[1024,2048], S=2 (grid 320), 16 chunks/split
    gemm_direct<0><<<dim3(D_ / 128, (B_ * N_) / 128, 2), 256, SMEM_TOTAL_GEMM>>>(
        ah_hi, ah_lo, W2, part, nullptr, nullptr, B_ * N_, D_, D_, H_, 16);
    reduce_convert_kernel<<<((int)((size_t)B_ * N_ * D_) + 255) / 256, 256>>>(
        part, 2, (size_t)B_ * N_ * D_, nd_hi, nd_lo);

    // fc_g: [256,10240]@Wg[10240,2048], S=10 (grid 320), 32 chunks/split
    gemm_direct<0><<<dim3(D_ / 128, B_ / 128, 10), 256, SMEM_TOTAL_GEMM>>>(
        nd_hi, nd_lo, Wg, part, nullptr, nullptr, B_, D_, D_, N_ * D_, 32);
    reduce_bias_convert_kernel<<<(B_ * D_ + 255) / 256, 256>>>(part, 10, B_, D_, bg, gg_hi, gg_lo);

    // fc_cls: [256,2048]@Wc[2048,1000->pad 1024], S=16 (grid 256), 4 chunks/split
    gemm_direct<0><<<dim3(NPAD_C / 128, B_ / 128, 16), 256, SMEM_TOTAL_GEMM>>>(
        gg_hi, gg_lo, Wc, part, nullptr, nullptr, B_, NPAD_C, C_, D_, 4);
    reduce_bias_out_kernel<<<(B_ * C_ + 255) / 256, 256>>>(part, 16, NPAD_C, bc, pred_out);

    // prototypes
    class_meta_kernel<<<1, 1024>>>(tgt);
    proto_update_kernel<<<(C_ * (D_ / 4) + 255) / 256, 256>>>(x, prot, proto_out);
}

// round 9
// speedup vs baseline: 5.3957x; 1.1166x over previous
#include <cuda_runtime.h>
#include <cuda_bf16.h>
#include <cstdint>

#define B_ 256
#define N_ 5
#define D_ 2048
#define C_ 1000
#define H_ 1024
#define NPAD_C 1024
#define PROTO_M 0.999f
#define EPS_ 1e-12f
#define GRID_G 296   // 148 SMs x 2 CTA slots

// ==================== scratch (static device globals) ====================
__device__ __nv_bfloat16 g_ax_hi[B_ * N_ * D_], g_ax_lo[B_ * N_ * D_];
__device__ __nv_bfloat16 g_ah_hi[B_ * N_ * H_], g_ah_lo[B_ * N_ * H_];
__device__ __nv_bfloat16 g_nd_hi[B_ * N_ * D_], g_nd_lo[B_ * N_ * D_];
__device__ __nv_bfloat16 g_g_hi[B_ * D_], g_g_lo[B_ * D_];
__device__ float g_part[GRID_G * 128 * 128];   // unit-major split-K partials (19.4MB)

__device__ float g_scale[C_];
__device__ int   g_off[C_ + 1];
__device__ int   g_idx[B_];
__device__ float g_w[B_];

// ==================== helpers ====================
__device__ __forceinline__ void split_bf16(float v, __nv_bfloat16& hi, __nv_bfloat16& lo) {
    hi = __float2bfloat16_rn(v);
    lo = __float2bfloat16_rn(v - __bfloat162float(hi));
}
__device__ __forceinline__ uint32_t smem_u32(const void* p) {
    uint32_t a;
    asm("{ .reg .u64 t; cvta.to.shared.u64 t, %1; cvt.u32.u64 %0, t; }" : "=r"(a) : "l"(p));
    return a;
}
__device__ __forceinline__ void cp_async16(uint32_t dst, const void* src) {
    asm volatile("cp.async.cg.shared.global [%0], [%1], 16;" :: "r"(dst), "l"(src));
}
__device__ __forceinline__ void cp_async16_z(uint32_t dst, const void* src, int sz) {
    asm volatile("cp.async.cg.shared.global [%0], [%1], 16, %2;" :: "r"(dst), "l"(src), "r"(sz));
}
__device__ __forceinline__ void cp_commit() { asm volatile("cp.async.commit_group;" ::: "memory"); }
__device__ __forceinline__ void cp_wait0() { asm volatile("cp.async.wait_group 0;" ::: "memory"); }

__device__ __forceinline__ void ldsm_x4(uint32_t* r, uint32_t addr) {
    asm volatile("ldmatrix.sync.aligned.m8n8.x4.shared.b16 {%0,%1,%2,%3}, [%4];"
        : "=r"(r[0]), "=r"(r[1]), "=r"(r[2]), "=r"(r[3]) : "r"(addr));
}
__device__ __forceinline__ void ldsm_x4_t(uint32_t* r, uint32_t addr) {
    asm volatile("ldmatrix.sync.aligned.m8n8.x4.trans.shared.b16 {%0,%1,%2,%3}, [%4];"
        : "=r"(r[0]), "=r"(r[1]), "=r"(r[2]), "=r"(r[3]) : "r"(addr));
}
__device__ __forceinline__ void mma16816(float* c, const uint32_t* a, uint32_t b0, uint32_t b1) {
    asm volatile(
        "mma.sync.aligned.m16n8k16.row.col.f32.bf16.bf16.f32 "
        "{%0,%1,%2,%3}, {%4,%5,%6,%7}, {%8,%9}, {%0,%1,%2,%3};"
        : "+f"(c[0]), "+f"(c[1]), "+f"(c[2]), "+f"(c[3])
        : "r"(a[0]), "r"(a[1]), "r"(a[2]), "r"(a[3]), "r"(b0), "r"(b1));
}

// tile -> (first unit, split count) under the variable-split decomposition
__device__ __forceinline__ int unit_base(int t, int q, int r, int& St) {
    if (t < r) { St = q + 1; return t * (q + 1); }
    St = q;
    return r * (q + 1) + (t - r) * q;
}
__device__ __forceinline__ float sum_tile(const float* __restrict__ P, int t, int lr, int lc,
                                          int q, int r) {
    int St;
    int ub = unit_base(t, q, r, St);
    const float* p = P + (size_t)ub * 16384 + lr * 128 + lc;
    float s = 0.f;
    for (int i = 0; i < St; i++) { s += *p; p += 16384; }
    return s;
}

// ==================== adj-mix + hi/lo convert ====================
__global__ void adjmix_convert_kernel(const float* __restrict__ in,
                                      const float* __restrict__ adj,
                                      __nv_bfloat16* __restrict__ hi,
                                      __nv_bfloat16* __restrict__ lo, int F) {
    int t = blockIdx.x * blockDim.x + threadIdx.x;
    if (t >= B_ * F) return;
    int b = t / F, f = t % F;
    float xv[N_];
#pragma unroll
    for (int m = 0; m < N_; m++) xv[m] = in[((size_t)b * N_ + m) * F + f];
#pragma unroll
    for (int n = 0; n < N_; n++) {
        float s = 0.f;
#pragma unroll
        for (int m = 0; m < N_; m++) s += adj[n * N_ + m] * xv[m];
        __nv_bfloat16 h, l;
        split_bf16(s, h, l);
        hi[((size_t)b * N_ + n) * F + f] = h;
        lo[((size_t)b * N_ + n) * F + f] = l;
    }
}

// ==================== HMMA GEMM, balanced unit decomposition ====================
// grid = GRID_G flat units; unit -> (tile, split) with per-tile split count q or q+1.
// Smem: Ahi@0, Alo@20480 (80B rows), Wf32@40960 (512B rows), Bhi@73728,
// Blo@91136 (272B rows). All double-buffered. Total 108544 B.
#define SMEM_TOTAL_GEMM 108544
__global__ void __launch_bounds__(256, 2)
gemm_units(const __nv_bfloat16* __restrict__ A_hi, const __nv_bfloat16* __restrict__ A_lo,
           const float* __restrict__ W, float* __restrict__ P,
           int Nw, int K, int NTx, int T, int Ct) {
    extern __shared__ __align__(16) uint8_t smem[];
    const uint32_t base = smem_u32(smem);
    const uint32_t oAhi = 0, oAlo = 20480, oW = 40960, oBhi = 73728, oBlo = 91136;
    const uint32_t strA = 10240, strW = 16384, strB = 8704;

    // ---- unit -> tile/split ----
    const int G = gridDim.x;
    const int q = G / T, r = G % T;
    const int u = blockIdx.x;
    const int thresh = r * (q + 1);
    int t, s, St;
    if (u < thresh) { St = q + 1; t = u / St; s = u - t * St; }
    else { int v = u - thresh; St = q; t = r + v / q; s = v - (v / q) * q; }
    const int c0 = (s * Ct) / St;
    const int NC = ((s + 1) * Ct) / St - c0;
    const int row0 = (t / NTx) * 128, col0 = (t % NTx) * 128;

    const int tid = threadIdx.x;
    const int lane = tid & 31, warp = tid >> 5;
    const int wr = warp & 3, wc = warp >> 2;     // 4x2 warp grid, warp tile 32x64

    const int ar0 = tid >> 2, aq0 = tid & 3;
    const int ar1 = (tid + 256) >> 2, aq1 = (tid + 256) & 3;
    int wk[4], wq[4], wsz[4];
#pragma unroll
    for (int i = 0; i < 4; i++) {
        int idx = tid + i * 256;
        wk[i] = idx >> 5; wq[i] = idx & 31;
        int v = (Nw - (col0 + wq[i] * 4)) * 4;
        wsz[i] = v < 0 ? 0 : (v > 16 ? 16 : v);
    }

    const int selRow = (lane & 7) + ((lane >> 3) & 1) * 8;
    const int selHi = (lane >> 4) & 1;
    const uint32_t aOff = (uint32_t)((wr * 32 + selRow) * 80 + selHi * 16);
    const uint32_t bOff = (uint32_t)(selRow * 272 + wc * 128 + selHi * 16);

    float acc[2][8][4] = {};

    auto stage = [&](int c, int buf) {
        int kk = c * 32;
        uint32_t da = base + oAhi + buf * strA;
        uint32_t dl = base + oAlo + buf * strA;
        uint32_t dw = base + oW + buf * strW;
        cp_async16(da + ar0 * 80 + aq0 * 16, A_hi + (size_t)(row0 + ar0) * K + kk + aq0 * 8);
        cp_async16(da + ar1 * 80 + aq1 * 16, A_hi + (size_t)(row0 + ar1) * K + kk + aq1 * 8);
        cp_async16(dl + ar0 * 80 + aq0 * 16, A_lo + (size_t)(row0 + ar0) * K + kk + aq0 * 8);
        cp_async16(dl + ar1 * 80 + aq1 * 16, A_lo + (size_t)(row0 + ar1) * K + kk + aq1 * 8);
#pragma unroll
        for (int i = 0; i < 4; i++) {
            const float* src = wsz[i] ? (W + (size_t)(kk + wk[i]) * Nw + col0 + wq[i] * 4) : W;
            cp_async16_z(dw + wk[i] * 512 + wq[i] * 16, src, wsz[i]);
        }
    };

    // convert W f32 tile (buf) -> bf16 hi/lo (buf); SELF-DATA only (safe after own cp_wait0)
    auto convert = [&](int buf) {
#pragma unroll
        for (int i = 0; i < 4; i++) {
            int idx = tid + i * 256;
            float4 v = *reinterpret_cast<const float4*>(smem + (oW + buf * strW) + idx * 16);
            __nv_bfloat16 h0, l0, h1, l1, h2, l2, h3, l3;
            split_bf16(v.x, h0, l0); split_bf16(v.y, h1, l1);
            split_bf16(v.z, h2, l2); split_bf16(v.w, h3, l3);
            __nv_bfloat162 hA, hB, lA, lB;
            hA.x = h0; hA.y = h1; hB.x = h2; hB.y = h3;
            lA.x = l0; lA.y = l1; lB.x = l2; lB.y = l3;
            uint2 hp = make_uint2(*reinterpret_cast<uint32_t*>(&hA),
                                  *reinterpret_cast<uint32_t*>(&hB));
            uint2 lp = make_uint2(*reinterpret_cast<uint32_t*>(&lA),
                                  *reinterpret_cast<uint32_t*>(&lB));
            uint32_t off = (uint32_t)(wk[i] * 272 + wq[i] * 8);
            *reinterpret_cast<uint2*>(smem + (oBhi + buf * strB) + off) = hp;
            *reinterpret_cast<uint2*>(smem + (oBlo + buf * strB) + off) = lp;
        }
    };

    // prologue
    stage(c0, 0);
    cp_commit();
    cp_wait0();
    convert(0);
    __syncthreads();
    if (NC > 1) { stage(c0 + 1, 1); cp_commit(); }

    for (int li = 0; li < NC; li++) {
        const int buf = li & 1;
        const uint32_t ah = base + oAhi + buf * strA, al = base + oAlo + buf * strA;
        const uint32_t bh = base + oBhi + buf * strB, bl = base + oBlo + buf * strB;

#pragma unroll
        for (int ks = 0; ks < 2; ks++) {
            uint32_t fa[2][4], fb1[4][4], fb2[4][4];
            ldsm_x4(fa[0], ah + aOff + ks * 32);
            ldsm_x4(fa[1], ah + aOff + 1280 + ks * 32);
#pragma unroll
            for (int p = 0; p < 4; p++) ldsm_x4_t(fb1[p], bh + bOff + ks * 4352 + p * 32);
#pragma unroll
            for (int mi = 0; mi < 2; mi++)
#pragma unroll
                for (int p = 0; p < 4; p++) {
                    mma16816(acc[mi][2 * p], fa[mi], fb1[p][0], fb1[p][1]);
                    mma16816(acc[mi][2 * p + 1], fa[mi], fb1[p][2], fb1[p][3]);
                }
#pragma unroll
            for (int p = 0; p < 4; p++) ldsm_x4_t(fb2[p], bl + bOff + ks * 4352 + p * 32);
#pragma unroll
            for (int mi = 0; mi < 2; mi++)
#pragma unroll
                for (int p = 0; p < 4; p++) {
                    mma16816(acc[mi][2 * p], fa[mi], fb2[p][0], fb2[p][1]);
                    mma16816(acc[mi][2 * p + 1], fa[mi], fb2[p][2], fb2[p][3]);
                }
            ldsm_x4(fa[0], al + aOff + ks * 32);
            ldsm_x4(fa[1], al + aOff + 1280 + ks * 32);
#pragma unroll
            for (int mi = 0; mi < 2; mi++)
#pragma unroll
                for (int p = 0; p < 4; p++) {
                    mma16816(acc[mi][2 * p], fa[mi], fb1[p][0], fb1[p][1]);
                    mma16816(acc[mi][2 * p + 1], fa[mi], fb1[p][2], fb1[p][3]);
                }
        }

        if (li + 1 < NC) {
            cp_wait0();
            convert(buf ^ 1);
        }
        __syncthreads();
        if (li + 2 < NC) { stage(c0 + li + 2, buf); cp_commit(); }
    }

    // epilogue: unit-major local tile block [128x128] f32
    const int g = lane >> 2, tg = lane & 3;
    float* up = P + (size_t)u * 16384;
#pragma unroll
    for (int mi = 0; mi < 2; mi++)
#pragma unroll
        for (int half = 0; half < 2; half++) {
            int lr = wr * 32 + mi * 16 + g + half * 8;
            float* rowp = up + lr * 128 + wc * 64;
#pragma unroll
            for (int ni = 0; ni < 8; ni++)
                *reinterpret_cast<float2*>(rowp + ni * 8 + tg * 2) =
                    make_float2(acc[mi][ni][half * 2], acc[mi][ni][half * 2 + 1]);
        }
}

// ==================== reduce epilogues (unit-major gather) ====================
// GEMM1: gather -> relu -> adj-mix -> hi/lo convert. Rows are (b*5+m), F=H, NTx=8.
__global__ void reduce_relu_adjmix_convert_kernel(const float* __restrict__ P,
                                                  const float* __restrict__ adj,
                                                  __nv_bfloat16* __restrict__ hi,
                                                  __nv_bfloat16* __restrict__ lo,
                                                  int F, int NTx, int q, int r) {
    int t = blockIdx.x * blockDim.x + threadIdx.x;
    if (t >= B_ * F) return;
    int b = t / F, f = t % F;
    float hv[N_];
#pragma unroll
    for (int m = 0; m < N_; m++) {
        int row = b * N_ + m;
        int tile = (row >> 7) * NTx + (f >> 7);
        hv[m] = fmaxf(sum_tile(P, tile, row & 127, f & 127, q, r), 0.f);
    }
#pragma unroll
    for (int n = 0; n < N_; n++) {
        float s = 0.f;
#pragma unroll
        for (int m = 0; m < N_; m++) s += adj[n * N_ + m] * hv[m];
        __nv_bfloat16 h, l;
        split_bf16(s, h, l);
        hi[((size_t)b * N_ + n) * F + f] = h;
        lo[((size_t)b * N_ + n) * F + f] = l;
    }
}

__global__ void reduce_convert_kernel(const float* __restrict__ P, int Mrows, int F,
                                      __nv_bfloat16* __restrict__ hi,
                                      __nv_bfloat16* __restrict__ lo,
                                      int NTx, int q, int r) {
    int t = blockIdx.x * blockDim.x + threadIdx.x;
    if (t >= Mrows * F) return;
    int row = t / F, f = t % F;
    int tile = (row >> 7) * NTx + (f >> 7);
    float s = sum_tile(P, tile, row & 127, f & 127, q, r);
    __nv_bfloat16 h, l;
    split_bf16(s, h, l);
    hi[t] = h;
    lo[t] = l;
}

__global__ void reduce_bias_convert_kernel(const float* __restrict__ P, int Mrows, int F,
                                           const float* __restrict__ bias,
                                           __nv_bfloat16* __restrict__ hi,
                                           __nv_bfloat16* __restrict__ lo,
                                           int NTx, int q, int r) {
    int t = blockIdx.x * blockDim.x + threadIdx.x;
    if (t >= Mrows * F) return;
    int row = t / F, f = t % F;
    int tile = (row >> 7) * NTx + (f >> 7);
    float s = bias[f] + sum_tile(P, tile, row & 127, f & 127, q, r);
    __nv_bfloat16 h, l;
    split_bf16(s, h, l);
    hi[t] = h;
    lo[t] = l;
}

__global__ void reduce_bias_out_kernel(const float* __restrict__ P,
                                       const float* __restrict__ bias,
                                       float* __restrict__ out,
                                       int NTx, int q, int r) {
    int t = blockIdx.x * blockDim.x + threadIdx.x;
    if (t >= B_ * C_) return;
    int b = t / C_, n = t % C_;
    int tile = (b >> 7) * NTx + (n >> 7);
    out[t] = bias[n] + sum_tile(P, tile, b & 127, n & 127, q, r);
}

// ==================== prototype EMA (closed form), parallel metadata ====================
__global__ void class_meta_kernel(const int* __restrict__ target) {  // 1 block, 1024 thr
    __shared__ int cnt[1024];
    __shared__ int scan[1024];
    __shared__ int t_s[B_];
    __shared__ int rank_s[B_];
    int tid = threadIdx.x;
    cnt[tid] = 0;
    __syncthreads();
    if (tid < B_) t_s[tid] = target[tid];
    __syncthreads();
    if (tid < B_) {
        int c = t_s[tid], r = 0;
        for (int j = 0; j < tid; j++) r += (t_s[j] == c) ? 1 : 0;
        rank_s[tid] = r;
        atomicAdd(&cnt[c], 1);
    }
    __syncthreads();
    if (tid < C_) g_scale[tid] = powf(PROTO_M, (float)cnt[tid]);
    scan[tid] = cnt[tid];
    __syncthreads();
    for (int ofs = 1; ofs < 1024; ofs <<= 1) {
        int v = (tid >= ofs) ? scan[tid - ofs] : 0;
        __syncthreads();
        scan[tid] += v;
        __syncthreads();
    }
    if (tid < C_) g_off[tid] = scan[tid] - cnt[tid];
    if (tid == 0) g_off[C_] = B_;
    __syncthreads();
    if (tid < B_) {
        int c = t_s[tid];
        int p = (scan[c] - cnt[c]) + rank_s[tid];
        g_idx[p] = tid;
        g_w[p] = (1.0f - PROTO_M) * powf(PROTO_M, (float)(cnt[c] - 1 - rank_s[tid]));
    }
}

__global__ void proto_update_kernel(const float* __restrict__ x,
                                    const float* __restrict__ protos,
                                    float* __restrict__ out) {
    int t = blockIdx.x * blockDim.x + threadIdx.x;
    const int D4 = D_ / 4;
    if (t >= C_ * D4) return;
    int c = t / D4, d4 = t % D4;
    float s = g_scale[c];
    float4 v[N_];
#pragma unroll
    for (int n = 0; n < N_; n++) {
        float4 p = *reinterpret_cast<const float4*>(protos + ((size_t)c * N_ + n) * D_ + d4 * 4);
        v[n] = make_float4(p.x * s, p.y * s, p.z * s, p.w * s);
    }
    int e = g_off[c + 1];
    for (int j = g_off[c]; j < e; j++) {
        int i = g_idx[j];
        float w = g_w[j];
#pragma unroll
        for (int n = 0; n < N_; n++) {
            float4 xv = *reinterpret_cast<const float4*>(x + ((size_t)i * N_ + n) * D_ + d4 * 4);
            v[n].x += w * xv.x; v[n].y += w * xv.y;
            v[n].z += w * xv.z; v[n].w += w * xv.w;
        }
    }
    float4 nrm4 = make_float4(0.f, 0.f, 0.f, 0.f);
#pragma unroll
    for (int n = 0; n < N_; n++) {
        nrm4.x += v[n].x * v[n].x; nrm4.y += v[n].y * v[n].y;
        nrm4.z += v[n].z * v[n].z; nrm4.w += v[n].w * v[n].w;
    }
    float4 inv = make_float4(1.f / fmaxf(sqrtf(nrm4.x), EPS_), 1.f / fmaxf(sqrtf(nrm4.y), EPS_),
                             1.f / fmaxf(sqrtf(nrm4.z), EPS_), 1.f / fmaxf(sqrtf(nrm4.w), EPS_));
#pragma unroll
    for (int n = 0; n < N_; n++) {
        float4 o = make_float4(v[n].x * inv.x, v[n].y * inv.y, v[n].z * inv.z, v[n].w * inv.w);
        *reinterpret_cast<float4*>(out + ((size_t)c * N_ + n) * D_ + d4 * 4) = o;
    }
}

// ==================== launch ====================
extern "C" void kernel_launch(void* const* d_in, const int* in_sizes, int n_in,
                              void* d_out, int out_size) {
    const float* x    = (const float*)d_in[0];
    const int*   tgt  = (const int*)d_in[1];
    const float* prot = (const float*)d_in[2];
    const float* adj  = (const float*)d_in[3];
    const float* W1   = (const float*)d_in[4];
    const float* W2   = (const float*)d_in[5];
    const float* Wg   = (const float*)d_in[6];
    const float* bg   = (const float*)d_in[7];
    const float* Wc   = (const float*)d_in[8];
    const float* bc   = (const float*)d_in[9];

    float* pred_out  = (float*)d_out;
    float* proto_out = (float*)d_out + (size_t)B_ * C_;

    __nv_bfloat16 *ax_hi, *ax_lo, *ah_hi, *ah_lo, *nd_hi, *nd_lo, *gg_hi, *gg_lo;
    float* part;
    cudaGetSymbolAddress((void**)&ax_hi, g_ax_hi);   cudaGetSymbolAddress((void**)&ax_lo, g_ax_lo);
    cudaGetSymbolAddress((void**)&ah_hi, g_ah_hi);   cudaGetSymbolAddress((void**)&ah_lo, g_ah_lo);
    cudaGetSymbolAddress((void**)&nd_hi, g_nd_hi);   cudaGetSymbolAddress((void**)&nd_lo, g_nd_lo);
    cudaGetSymbolAddress((void**)&gg_hi, g_g_hi);    cudaGetSymbolAddress((void**)&gg_lo, g_g_lo);
    cudaGetSymbolAddress((void**)&part, g_part);

    cudaFuncSetAttribute(gemm_units, cudaFuncAttributeMaxDynamicSharedMemorySize, SMEM_TOTAL_GEMM);

    // ax = adj @ x (+ hi/lo convert)
    adjmix_convert_kernel<<<(B_ * D_ + 255) / 256, 256>>>(x, adj, ax_hi, ax_lo, D_);

    // GEMM1: [1280,2048]@W1[2048,1024]. T=80 tiles (10x8), Ct=64. q=3,r=56.
    gemm_units<<<GRID_G, 256, SMEM_TOTAL_GEMM>>>(ax_hi, ax_lo, W1, part, H_, D_, 8, 80, 64);
    reduce_relu_adjmix_convert_kernel<<<(B_ * H_ + 255) / 256, 256>>>(
        part, adj, ah_hi, ah_lo, H_, 8, GRID_G / 80, GRID_G % 80);

    // GEMM2: [1280,1024]@W2[1024,2048]. T=160 (10x16), Ct=32. q=1,r=136.
    gemm_units<<<GRID_G, 256, SMEM_TOTAL_GEMM>>>(ah_hi, ah_lo, W2, part, D_, H_, 16, 160, 32);
    reduce_convert_kernel<<<(B_ * N_ * D_ + 255) / 256, 256>>>(
        part, B_ * N_, D_, nd_hi, nd_lo, 16, GRID_G / 160, GRID_G % 160);

    // fc_g: [256,10240]@Wg[10240,2048]. T=32 (2x16), Ct=320. q=9,r=8.
    gemm_units<<<GRID_G, 256, SMEM_TOTAL_GEMM>>>(nd_hi, nd_lo, Wg, part, D_, N_ * D_, 16, 32, 320);
    reduce_bias_convert_kernel<<<(B_ * D_ + 255) / 256, 256>>>(
        part, B_, D_, bg, gg_hi, gg_lo, 16, GRID_G / 32, GRID_G % 32);

    // fc_cls: [256,2048]@Wc[2048,1000 pad 1024]. T=16 (2x8), Ct=64. q=18,r=8.
    gemm_units<<<GRID_G, 256, SMEM_TOTAL_GEMM>>>(gg_hi, gg_lo, Wc, part, C_, D_, 8, 16, 64);
    reduce_bias_out_kernel<<<(B_ * C_ + 255) / 256, 256>>>(
        part, bc, pred_out, 8, GRID_G / 16, GRID_G % 16);

    // prototypes
    class_meta_kernel<<<1, 1024>>>(tgt);
    proto_update_kernel<<<(C_ * (D_ / 4) + 255) / 256, 256>>>(x, prot, proto_out);
}